// round 1
// baseline (speedup 1.0000x reference)
#include <cuda_runtime.h>
#include <cstdint>

#define SEQ 512
#define DIN 512
#define MEM 256
#define HID 512
#define NBATCH 64

// ---------------- scratch (static device memory; no allocations) ----------------
__device__ float g_u[NBATCH * SEQ];          // relu(x @ Wu + b)
__device__ float g_Ht[SEQ * MEM];            // Ht[d][m] = (A^d B)[m]
__device__ float g_AT[2][MEM * MEM];         // ping-pong: (A^n)^T, AT[k][m] = A^n[m][k]
__device__ float g_G[SEQ * HID];             // G[d][j] = sum_m Ht[d][m] * Wh_w[m][j]

// ---------------- kernel 1: u = relu(x @ Wu_w + Wu_b) ----------------
__global__ __launch_bounds__(256) void k_u(const float* __restrict__ x,
                                           const float* __restrict__ wu,
                                           const float* __restrict__ wub) {
    int row = blockIdx.x * 8 + (threadIdx.x >> 5);   // [0, 32768)
    int lane = threadIdx.x & 31;
    const float4* xr = (const float4*)(x + (size_t)row * DIN);
    const float4* wr = (const float4*)wu;
    float s = 0.f;
#pragma unroll
    for (int i = 0; i < 4; i++) {
        float4 v = xr[lane + 32 * i];
        float4 w = wr[lane + 32 * i];
        s += v.x * w.x + v.y * w.y + v.z * w.z + v.w * w.w;
    }
#pragma unroll
    for (int o = 16; o; o >>= 1) s += __shfl_xor_sync(0xffffffffu, s, o);
    if (lane == 0) g_u[row] = fmaxf(s + wub[0], 0.f);
}

// ---------------- kernel 2: AT0 = A^T ; Ht[0] = B ----------------
__global__ __launch_bounds__(256) void k_init(const float* __restrict__ A,
                                              const float* __restrict__ B) {
    int k = blockIdx.x;       // 256
    int m = threadIdx.x;      // 256
    g_AT[0][k * MEM + m] = A[m * MEM + k];
    if (k == 0) g_Ht[m] = B[m];
}

// ---------------- kernel 3: doubling round ----------------
// Given AT[sel] = (A^n)^T and Ht rows [0,n):
//   blocks [0,16):   A2nT[j][m] = sum_k AnT[j][k] * AnT[k][m]      -> AT[sel^1]
//   blocks [16,...): Ht[n+d][m] = sum_k Ht[d][k]  * AnT[k][m]      (d < n)
__global__ __launch_bounds__(256) void k_round(int sel, int n) {
    __shared__ float As[8][64];
    __shared__ float Bs[8][64];
    const float* __restrict__ ATin = g_AT[sel];
    const float* Amat;
    float* Cmat;
    int rows, tr, tc;
    if (blockIdx.x < 16) {
        Amat = ATin; Cmat = g_AT[sel ^ 1]; rows = MEM;
        tr = blockIdx.x >> 2; tc = blockIdx.x & 3;
    } else {
        int bi = blockIdx.x - 16;
        Amat = g_Ht; Cmat = g_Ht + (size_t)n * MEM; rows = n;
        tr = bi >> 2; tc = bi & 3;
    }
    int r0 = tr * 64, c0 = tc * 64;
    int tid = threadIdx.x;
    int tx = tid & 15, ty = tid >> 4;
    int ar = tid >> 2, ak = (tid & 3) * 2;     // A chunk: 64 rows x 8 k
    int bk = tid >> 5, bj = (tid & 31) * 2;    // B chunk: 8 k x 64 cols
    float acc[4][4] = {};
    for (int k0 = 0; k0 < MEM; k0 += 8) {
        float2 av = make_float2(0.f, 0.f);
        int arow = r0 + ar;
        if (arow < rows) av = *(const float2*)(Amat + (size_t)arow * MEM + k0 + ak);
        float2 bv = *(const float2*)(ATin + (size_t)(k0 + bk) * MEM + c0 + bj);
        __syncthreads();
        As[ak][ar] = av.x; As[ak + 1][ar] = av.y;
        *(float2*)&Bs[bk][bj] = bv;
        __syncthreads();
#pragma unroll
        for (int k = 0; k < 8; k++) {
            float a[4], b[4];
            *(float4*)a = *(const float4*)&As[k][ty * 4];
            *(float4*)b = *(const float4*)&Bs[k][tx * 4];
#pragma unroll
            for (int i = 0; i < 4; i++)
#pragma unroll
                for (int j = 0; j < 4; j++) acc[i][j] = fmaf(a[i], b[j], acc[i][j]);
        }
    }
#pragma unroll
    for (int i = 0; i < 4; i++) {
        int row = r0 + ty * 4 + i;
        if (row < rows)
#pragma unroll
            for (int j = 0; j < 4; j++)
                Cmat[(size_t)row * MEM + c0 + tx * 4 + j] = acc[i][j];
    }
}

// ---------------- kernel 4: G = Ht @ Wh_m   (512x256 @ 256x512) ----------------
__global__ __launch_bounds__(256) void k_G(const float* __restrict__ Wh) {
    __shared__ float As[8][64];
    __shared__ float Bs[8][64];
    int r0 = blockIdx.y * 64, c0 = blockIdx.x * 64;
    int tid = threadIdx.x;
    int tx = tid & 15, ty = tid >> 4;
    int ar = tid >> 2, ak = (tid & 3) * 2;
    int bk = tid >> 5, bj = (tid & 31) * 2;
    float acc[4][4] = {};
    for (int k0 = 0; k0 < MEM; k0 += 8) {
        float2 av = *(const float2*)(g_Ht + (size_t)(r0 + ar) * MEM + k0 + ak);
        float2 bv = *(const float2*)(Wh + (size_t)(k0 + bk) * HID + c0 + bj);
        __syncthreads();
        As[ak][ar] = av.x; As[ak + 1][ar] = av.y;
        *(float2*)&Bs[bk][bj] = bv;
        __syncthreads();
#pragma unroll
        for (int k = 0; k < 8; k++) {
            float a[4], b[4];
            *(float4*)a = *(const float4*)&As[k][ty * 4];
            *(float4*)b = *(const float4*)&Bs[k][tx * 4];
#pragma unroll
            for (int i = 0; i < 4; i++)
#pragma unroll
                for (int j = 0; j < 4; j++) acc[i][j] = fmaf(a[i], b[j], acc[i][j]);
        }
    }
#pragma unroll
    for (int i = 0; i < 4; i++)
#pragma unroll
        for (int j = 0; j < 4; j++)
            g_G[(size_t)(r0 + ty * 4 + i) * HID + c0 + tx * 4 + j] = acc[i][j];
}

// ---------------- kernel 5: fused main GEMM ----------------
// h[b,t,j] = relu( sum_k x[b,t,k]*Wh[256+k][j]  +  sum_{d=0}^{t} u[b,t-d]*G[d][j]  + bias[j] )
// h_n[b,j] = h[b,511,j]
__global__ __launch_bounds__(256, 2) void k_main(const float* __restrict__ x,
                                                 const float* __restrict__ Wh,
                                                 const float* __restrict__ Whb,
                                                 float* __restrict__ out,
                                                 int write_hn) {
    __shared__ float As[8][128];
    __shared__ float Bs[8][128];
    __shared__ float ush[SEQ];
    const int b = blockIdx.z;
    const int t0 = blockIdx.y * 128;
    const int j0 = blockIdx.x * 128;
    const int tid = threadIdx.x;
    const int tx = tid & 15, ty = tid >> 4;
    const int ar = tid >> 1, ak4 = (tid & 1) * 4;   // A chunk: 128 rows x 8 k
    const int bk = tid >> 5, bj4 = (tid & 31) * 4;  // B chunk: 8 k x 128 j
    const int ulen = t0 + 128;

    for (int i = tid; i < ulen; i += 256) ush[i] = g_u[b * SEQ + i];
    __syncthreads();

    float acc[8][8] = {};
    const float* xb = x + (size_t)b * SEQ * DIN;

    // ---- phase 1: dense  x @ Wh_x ----
    for (int k0 = 0; k0 < DIN; k0 += 8) {
        float4 av = *(const float4*)(xb + (size_t)(t0 + ar) * DIN + k0 + ak4);
        float4 bv = *(const float4*)(Wh + (size_t)(MEM + k0 + bk) * HID + j0 + bj4);
        __syncthreads();
        As[ak4 + 0][ar] = av.x; As[ak4 + 1][ar] = av.y;
        As[ak4 + 2][ar] = av.z; As[ak4 + 3][ar] = av.w;
        *(float4*)&Bs[bk][bj4] = bv;
        __syncthreads();
#pragma unroll
        for (int k = 0; k < 8; k++) {
            float a[8], bb[8];
            *(float4*)a       = *(const float4*)&As[k][ty * 8];
            *(float4*)(a + 4) = *(const float4*)&As[k][ty * 8 + 4];
            *(float4*)bb       = *(const float4*)&Bs[k][tx * 8];
            *(float4*)(bb + 4) = *(const float4*)&Bs[k][tx * 8 + 4];
#pragma unroll
            for (int i = 0; i < 8; i++)
#pragma unroll
                for (int j = 0; j < 8; j++) acc[i][j] = fmaf(a[i], bb[j], acc[i][j]);
        }
    }

    // ---- phase 2: causal Toeplitz  u (*) G ----
    for (int d0 = 0; d0 < ulen; d0 += 8) {
        float a4[4];
#pragma unroll
        for (int i = 0; i < 4; i++) {
            int idx = t0 + ar - (d0 + ak4 + i);
            a4[i] = (idx >= 0) ? ush[idx] : 0.f;
        }
        float4 bv = *(const float4*)(g_G + (size_t)(d0 + bk) * HID + j0 + bj4);
        __syncthreads();
        As[ak4 + 0][ar] = a4[0]; As[ak4 + 1][ar] = a4[1];
        As[ak4 + 2][ar] = a4[2]; As[ak4 + 3][ar] = a4[3];
        *(float4*)&Bs[bk][bj4] = bv;
        __syncthreads();
#pragma unroll
        for (int k = 0; k < 8; k++) {
            float a[8], bb[8];
            *(float4*)a       = *(const float4*)&As[k][ty * 8];
            *(float4*)(a + 4) = *(const float4*)&As[k][ty * 8 + 4];
            *(float4*)bb       = *(const float4*)&Bs[k][tx * 8];
            *(float4*)(bb + 4) = *(const float4*)&Bs[k][tx * 8 + 4];
#pragma unroll
            for (int i = 0; i < 8; i++)
#pragma unroll
                for (int j = 0; j < 8; j++) acc[i][j] = fmaf(a[i], bb[j], acc[i][j]);
        }
    }

    // ---- epilogue: bias + relu, write h and h_n ----
    const size_t HN_BASE = (size_t)NBATCH * SEQ * HID;   // 16777216
#pragma unroll
    for (int i = 0; i < 8; i++) {
        int t = t0 + ty * 8 + i;
        size_t rowbase = ((size_t)b * SEQ + t) * HID;
#pragma unroll
        for (int j4 = 0; j4 < 8; j4 += 4) {
            int j = j0 + tx * 8 + j4;
            float4 v;
            v.x = fmaxf(acc[i][j4 + 0] + Whb[j + 0], 0.f);
            v.y = fmaxf(acc[i][j4 + 1] + Whb[j + 1], 0.f);
            v.z = fmaxf(acc[i][j4 + 2] + Whb[j + 2], 0.f);
            v.w = fmaxf(acc[i][j4 + 3] + Whb[j + 3], 0.f);
            *(float4*)(out + rowbase + j) = v;
            if (write_hn && t == SEQ - 1)
                *(float4*)(out + HN_BASE + (size_t)b * HID + j) = v;
        }
    }
}

// ---------------- launch ----------------
extern "C" void kernel_launch(void* const* d_in, const int* in_sizes, int n_in,
                              void* d_out, int out_size) {
    const float* x    = (const float*)d_in[0];
    const float* Wu_w = (const float*)d_in[1];
    const float* Wu_b = (const float*)d_in[2];
    const float* Wh_w = (const float*)d_in[3];
    const float* Wh_b = (const float*)d_in[4];
    const float* A    = (const float*)d_in[5];
    const float* B    = (const float*)d_in[6];
    float* out = (float*)d_out;

    int write_hn = (out_size >= NBATCH * SEQ * HID + NBATCH * HID) ? 1 : 0;

    k_u<<<NBATCH * SEQ / 8, 256>>>(x, Wu_w, Wu_b);
    k_init<<<MEM, 256>>>(A, B);
    int sel = 0;
    for (int n = 1; n <= 256; n <<= 1) {
        int blocks = 16 + ((n + 63) / 64) * 4;
        k_round<<<blocks, 256>>>(sel, n);
        sel ^= 1;
    }
    k_G<<<dim3(HID / 64, SEQ / 64), 256>>>(Wh_w);
    k_main<<<dim3(HID / 128, SEQ / 128, NBATCH), 256>>>(x, Wh_w, Wh_b, out, write_hn);
}

// round 4
// speedup vs baseline: 2.0890x; 2.0890x over previous
#include <cuda_runtime.h>
#include <cuda_bf16.h>
#include <cstdint>

#define SEQ 512
#define DIN 512
#define MEM 256
#define HID 512
#define NBATCH 64
#define URPAD 640

#define RSB 80                   // padded row stride bytes (40 bf16) for 32-col tiles
#define TILEB (128 * RSB)        // 10240 B per tile
#define BUFB (4 * TILEB)         // Ahi, Alo, Bhi, Blo
#define URS_OFF (2 * BUFB)       // smem offset of ur copy
#define SMEM_DYN (2 * BUFB + 2 * 1280)

// ---------------- static device scratch ----------------
__device__ __align__(16) __nv_bfloat16 g_xhi[NBATCH * SEQ * DIN];
__device__ __align__(16) __nv_bfloat16 g_xlo[NBATCH * SEQ * DIN];
__device__ __align__(16) __nv_bfloat16 g_urhi[NBATCH * URPAD];
__device__ __align__(16) __nv_bfloat16 g_urlo[NBATCH * URPAD];
__device__ __align__(16) __nv_bfloat16 g_whthi[HID * DIN];   // Wht[j][k] = Wh[256+k][j]
__device__ __align__(16) __nv_bfloat16 g_whtlo[HID * DIN];
__device__ __align__(16) __nv_bfloat16 g_gthi[HID * SEQ];    // Gt[j][d] = G[d][j]
__device__ __align__(16) __nv_bfloat16 g_gtlo[HID * SEQ];
__device__ float g_Ht[SEQ * MEM];
__device__ float g_AT[2][MEM * MEM];

// ---------------- helpers ----------------
__device__ __forceinline__ uint32_t smem_to_u32(const void* p) {
    uint32_t a;
    asm("{ .reg .u64 t; cvta.to.shared.u64 t, %1; cvt.u32.u64 %0, t; }" : "=r"(a) : "l"(p));
    return a;
}
__device__ __forceinline__ void cp16(uint32_t dst, const void* src) {
    asm volatile("cp.async.cg.shared.global [%0], [%1], 16;" :: "r"(dst), "l"(src));
}
#define CP_COMMIT() asm volatile("cp.async.commit_group;" ::: "memory")
#define CP_WAIT0()  asm volatile("cp.async.wait_group 0;" ::: "memory")
#define CP_WAIT1()  asm volatile("cp.async.wait_group 1;" ::: "memory")

__device__ __forceinline__ void ldsm4(uint32_t r[4], uint32_t addr) {
    asm volatile("ldmatrix.sync.aligned.m8n8.x4.shared.b16 {%0,%1,%2,%3}, [%4];"
                 : "=r"(r[0]), "=r"(r[1]), "=r"(r[2]), "=r"(r[3]) : "r"(addr));
}
__device__ __forceinline__ void mma_bf16(float* c, const uint32_t* a, const uint32_t* b) {
    asm volatile(
        "mma.sync.aligned.m16n8k16.row.col.f32.bf16.bf16.f32 "
        "{%0,%1,%2,%3}, {%4,%5,%6,%7}, {%8,%9}, {%0,%1,%2,%3};"
        : "+f"(c[0]), "+f"(c[1]), "+f"(c[2]), "+f"(c[3])
        : "r"(a[0]), "r"(a[1]), "r"(a[2]), "r"(a[3]), "r"(b[0]), "r"(b[1]));
}
__device__ __forceinline__ void split2(float v, __nv_bfloat16& h, __nv_bfloat16& l) {
    h = __float2bfloat16(v);
    l = __float2bfloat16(v - __bfloat162float(h));
}

// ---------------- k_u: u = relu(x@Wu+b) -> reversed split ur ----------------
__global__ __launch_bounds__(256) void k_u(const float* __restrict__ x,
                                           const float* __restrict__ wu,
                                           const float* __restrict__ wub) {
    int row = blockIdx.x * 8 + (threadIdx.x >> 5);
    int lane = threadIdx.x & 31;
    const float4* xr = (const float4*)(x + (size_t)row * DIN);
    const float4* wr = (const float4*)wu;
    float s = 0.f;
#pragma unroll
    for (int i = 0; i < 4; i++) {
        float4 v = xr[lane + 32 * i];
        float4 w = wr[lane + 32 * i];
        s += v.x * w.x + v.y * w.y + v.z * w.z + v.w * w.w;
    }
#pragma unroll
    for (int o = 16; o; o >>= 1) s += __shfl_xor_sync(0xffffffffu, s, o);
    if (lane == 0) {
        float u = fmaxf(s + wub[0], 0.f);
        int b = row >> 9, t = row & 511;
        __nv_bfloat16 h, l; split2(u, h, l);
        g_urhi[b * URPAD + (511 - t)] = h;
        g_urlo[b * URPAD + (511 - t)] = l;
    }
}

__global__ void k_pad() {
    int b = blockIdx.x, i = threadIdx.x;
    g_urhi[b * URPAD + 512 + i] = __float2bfloat16(0.f);
    g_urlo[b * URPAD + 512 + i] = __float2bfloat16(0.f);
}

// ---------------- k_split_x ----------------
__global__ __launch_bounds__(256) void k_split_x(const float* __restrict__ x) {
    size_t i = ((size_t)blockIdx.x * 256 + threadIdx.x) * 4;
    float4 v = *(const float4*)(x + i);
    __nv_bfloat16 h0, h1, h2, h3, l0, l1, l2, l3;
    split2(v.x, h0, l0); split2(v.y, h1, l1); split2(v.z, h2, l2); split2(v.w, h3, l3);
    __nv_bfloat162 ha = {h0, h1}, hb = {h2, h3}, la = {l0, l1}, lb = {l2, l3};
    *(__nv_bfloat162*)(g_xhi + i) = ha; *(__nv_bfloat162*)(g_xhi + i + 2) = hb;
    *(__nv_bfloat162*)(g_xlo + i) = la; *(__nv_bfloat162*)(g_xlo + i + 2) = lb;
}

// ---------------- k_wt: transpose+split Wh_x ----------------
__global__ __launch_bounds__(256) void k_wt(const float* __restrict__ Wh) {
    __shared__ float tile[32][33];
    int kb = blockIdx.x, jb = blockIdx.y;
    int tx = threadIdx.x & 31, ty = threadIdx.x >> 5;
    for (int yy = ty; yy < 32; yy += 8)
        tile[yy][tx] = Wh[(size_t)(MEM + kb * 32 + yy) * HID + jb * 32 + tx];
    __syncthreads();
    for (int yy = ty; yy < 32; yy += 8) {
        float v = tile[tx][yy];
        int j = jb * 32 + yy, k = kb * 32 + tx;
        __nv_bfloat16 h, l; split2(v, h, l);
        g_whthi[(size_t)j * DIN + k] = h;
        g_whtlo[(size_t)j * DIN + k] = l;
    }
}

// ---------------- k_init ----------------
__global__ __launch_bounds__(256) void k_init(const float* __restrict__ A,
                                              const float* __restrict__ B) {
    int k = blockIdx.x, m = threadIdx.x;
    g_AT[0][k * MEM + m] = A[m * MEM + k];
    if (k == 0) g_Ht[m] = B[m];
}

// ---------------- k_round: doubling (32x32 tiles) ----------------
__global__ __launch_bounds__(256) void k_round(int sel, int n) {
    __shared__ float As[16][32];
    __shared__ float Bs[16][33];
    const float* __restrict__ ATin = g_AT[sel];
    const float* Amat; float* Cmat; int rows;
    int bi = blockIdx.x;
    if (bi < 64) { Amat = ATin; Cmat = g_AT[sel ^ 1]; rows = MEM; }
    else { bi -= 64; Amat = g_Ht; Cmat = g_Ht + (size_t)n * MEM; rows = n; }
    int r0 = (bi >> 3) * 32, c0 = (bi & 7) * 32;
    int tid = threadIdx.x;
    int ar = tid >> 3, ac2 = (tid & 7) * 2;
    int bk = tid >> 4, bj2 = (tid & 15) * 2;
    int ty = tid >> 4, tx = tid & 15;
    float acc[2][2] = {};
    for (int k0 = 0; k0 < MEM; k0 += 16) {
        float2 av = make_float2(0.f, 0.f);
        if (r0 + ar < rows) av = *(const float2*)(Amat + (size_t)(r0 + ar) * MEM + k0 + ac2);
        float2 bv = *(const float2*)(ATin + (size_t)(k0 + bk) * MEM + c0 + bj2);
        __syncthreads();
        As[ac2][ar] = av.x; As[ac2 + 1][ar] = av.y;
        Bs[bk][bj2] = bv.x; Bs[bk][bj2 + 1] = bv.y;
        __syncthreads();
#pragma unroll
        for (int k = 0; k < 16; k++) {
            float a0 = As[k][ty * 2], a1 = As[k][ty * 2 + 1];
            float b0 = Bs[k][tx * 2], b1 = Bs[k][tx * 2 + 1];
            acc[0][0] = fmaf(a0, b0, acc[0][0]); acc[0][1] = fmaf(a0, b1, acc[0][1]);
            acc[1][0] = fmaf(a1, b0, acc[1][0]); acc[1][1] = fmaf(a1, b1, acc[1][1]);
        }
    }
#pragma unroll
    for (int i = 0; i < 2; i++) {
        int r = r0 + ty * 2 + i;
        if (r < rows) {
            Cmat[(size_t)r * MEM + c0 + tx * 2 + 0] = acc[i][0];
            Cmat[(size_t)r * MEM + c0 + tx * 2 + 1] = acc[i][1];
        }
    }
}

// ---------------- k_G: G=Ht@Wh_m -> transposed split gt ----------------
__global__ __launch_bounds__(256) void k_G(const float* __restrict__ Wh) {
    __shared__ float As[16][32];
    __shared__ float Bs[16][33];
    int r0 = blockIdx.y * 32, c0 = blockIdx.x * 32;
    int tid = threadIdx.x;
    int ar = tid >> 3, ac2 = (tid & 7) * 2;
    int bk = tid >> 4, bj2 = (tid & 15) * 2;
    int ty = tid >> 4, tx = tid & 15;
    float acc[2][2] = {};
    for (int k0 = 0; k0 < MEM; k0 += 16) {
        float2 av = *(const float2*)(g_Ht + (size_t)(r0 + ar) * MEM + k0 + ac2);
        float2 bv = *(const float2*)(Wh + (size_t)(k0 + bk) * HID + c0 + bj2);
        __syncthreads();
        As[ac2][ar] = av.x; As[ac2 + 1][ar] = av.y;
        Bs[bk][bj2] = bv.x; Bs[bk][bj2 + 1] = bv.y;
        __syncthreads();
#pragma unroll
        for (int k = 0; k < 16; k++) {
            float a0 = As[k][ty * 2], a1 = As[k][ty * 2 + 1];
            float b0 = Bs[k][tx * 2], b1 = Bs[k][tx * 2 + 1];
            acc[0][0] = fmaf(a0, b0, acc[0][0]); acc[0][1] = fmaf(a0, b1, acc[0][1]);
            acc[1][0] = fmaf(a1, b0, acc[1][0]); acc[1][1] = fmaf(a1, b1, acc[1][1]);
        }
    }
#pragma unroll
    for (int i = 0; i < 2; i++)
#pragma unroll
        for (int jj = 0; jj < 2; jj++) {
            int d = r0 + ty * 2 + i, j = c0 + tx * 2 + jj;
            __nv_bfloat16 h, l; split2(acc[i][jj], h, l);
            g_gthi[(size_t)j * SEQ + d] = h;
            g_gtlo[(size_t)j * SEQ + d] = l;
        }
}

// ---------------- k_main: mma.sync bf16 fused GEMM ----------------
__device__ __forceinline__ void cp_tile(uint32_t sdst, const __nv_bfloat16* __restrict__ g,
                                        int stride, int tid) {
#pragma unroll
    for (int it = 0; it < 2; it++) {
        int q = tid + it * 256;
        int row = q >> 2, ch = q & 3;
        cp16(sdst + row * RSB + ch * 16, g + (size_t)row * stride + ch * 8);
    }
}

__global__ __launch_bounds__(256) void k_main(const float* __restrict__ Whb,
                                              float* __restrict__ out, int write_hn) {
    extern __shared__ __align__(128) char smem[];
    const int b = blockIdx.z;
    const int t0 = blockIdx.y * 128;
    const int j0 = blockIdx.x * 128;
    const int tid = threadIdx.x;
    const int lane = tid & 31;
    const int warp_m = (tid >> 5) & 1;       // 2 warps in M
    const int warp_n = tid >> 6;             // 4 warps in N
    const uint32_t sbase = smem_to_u32(smem);

    // copy reversed u into smem (hi at URS_OFF, lo at +1280)
    {
        const uint32_t* gh = (const uint32_t*)(g_urhi + (size_t)b * URPAD);
        const uint32_t* gl = (const uint32_t*)(g_urlo + (size_t)b * URPAD);
        uint32_t* sh = (uint32_t*)(smem + URS_OFF);
        uint32_t* sl = (uint32_t*)(smem + URS_OFF + 1280);
        for (int q = tid; q < 320; q += 256) { sh[q] = gh[q]; sl[q] = gl[q]; }
    }
    __syncthreads();
    const uint32_t* ursh32 = (const uint32_t*)(smem + URS_OFF);
    const uint32_t* ursl32 = (const uint32_t*)(smem + URS_OFF + 1280);

    const __nv_bfloat16* xh = g_xhi + ((size_t)(b * SEQ + t0)) * DIN;
    const __nv_bfloat16* xl = g_xlo + ((size_t)(b * SEQ + t0)) * DIN;
    const __nv_bfloat16* wh = g_whthi + (size_t)j0 * DIN;
    const __nv_bfloat16* wl = g_whtlo + (size_t)j0 * DIN;
    const __nv_bfloat16* gh = g_gthi + (size_t)j0 * SEQ;
    const __nv_bfloat16* gl = g_gtlo + (size_t)j0 * SEQ;

    const int nchunks = 16 + 4 * (blockIdx.y + 1);

    // ---- fill one chunk into buffer p ----
    auto fill = [&](int i, int p) {
        uint32_t sb = sbase + p * BUFB;
        char* sc = smem + p * BUFB;
        if (i < 16) {
            int k0 = i * 32;
            cp_tile(sb,              xh + k0, DIN, tid);
            cp_tile(sb + TILEB,      xl + k0, DIN, tid);
            cp_tile(sb + 2 * TILEB,  wh + k0, DIN, tid);
            cp_tile(sb + 3 * TILEB,  wl + k0, DIN, tid);
        } else {
            int d0 = (i - 16) * 32;
            cp_tile(sb + 2 * TILEB,  gh + d0, SEQ, tid);
            cp_tile(sb + 3 * TILEB,  gl + d0, SEQ, tid);
            // Toeplitz A from smem ur copy
            int r = tid >> 1, half = tid & 1;
            int s0 = 511 - (t0 + r) + d0 + half * 16;
            int base = s0 >> 1, par = s0 & 1;
            uint32_t w[8];
            uint32_t w0 = ursh32[base];
#pragma unroll
            for (int c = 0; c < 8; c++) {
                uint32_t w1 = ursh32[base + c + 1];
                w[c] = par ? __byte_perm(w0, w1, 0x5432) : w0;
                w0 = w1;
            }
            *(uint4*)(sc + r * RSB + half * 32)      = make_uint4(w[0], w[1], w[2], w[3]);
            *(uint4*)(sc + r * RSB + half * 32 + 16) = make_uint4(w[4], w[5], w[6], w[7]);
            w0 = ursl32[base];
#pragma unroll
            for (int c = 0; c < 8; c++) {
                uint32_t w1 = ursl32[base + c + 1];
                w[c] = par ? __byte_perm(w0, w1, 0x5432) : w0;
                w0 = w1;
            }
            *(uint4*)(sc + TILEB + r * RSB + half * 32)      = make_uint4(w[0], w[1], w[2], w[3]);
            *(uint4*)(sc + TILEB + r * RSB + half * 32 + 16) = make_uint4(w[4], w[5], w[6], w[7]);
        }
    };

    float acc[4][4][4];
#pragma unroll
    for (int mi = 0; mi < 4; mi++)
#pragma unroll
        for (int ni = 0; ni < 4; ni++)
#pragma unroll
            for (int e = 0; e < 4; e++) acc[mi][ni][e] = 0.f;

    fill(0, 0);
    CP_COMMIT();

    for (int i = 0; i < nchunks; i++) {
        int p = i & 1;
        if (i + 1 < nchunks) { fill(i + 1, p ^ 1); CP_COMMIT(); CP_WAIT1(); }
        else CP_WAIT0();
        __syncthreads();

        uint32_t Abase = sbase + p * BUFB;
        uint32_t Bbase = Abase + 2 * TILEB;
#pragma unroll
        for (int ks = 0; ks < 2; ks++) {
            // B operand: stored N x K row-major (k contiguous) == "col" layout.
            // Plain ldmatrix, same addressing style as A.
            uint32_t bh[4][2], bl[4][2];
#pragma unroll
            for (int np = 0; np < 2; np++) {
                uint32_t r[4];
                uint32_t baddr = Bbase +
                    (warp_n * 32 + np * 16 + (lane & 15)) * RSB +
                    ks * 32 + ((lane >> 4) << 4);
                ldsm4(r, baddr);
                bh[np * 2][0] = r[0];     bh[np * 2][1] = r[2];
                bh[np * 2 + 1][0] = r[1]; bh[np * 2 + 1][1] = r[3];
                ldsm4(r, baddr + TILEB);
                bl[np * 2][0] = r[0];     bl[np * 2][1] = r[2];
                bl[np * 2 + 1][0] = r[1]; bl[np * 2 + 1][1] = r[3];
            }
            uint32_t a[4][4];
            uint32_t aoff = (warp_m * 64 + (lane & 15)) * RSB + ks * 32 + ((lane >> 4) << 4);
#pragma unroll
            for (int mi = 0; mi < 4; mi++) ldsm4(a[mi], Abase + aoff + mi * 16 * RSB);
#pragma unroll
            for (int mi = 0; mi < 4; mi++)
#pragma unroll
                for (int ni = 0; ni < 4; ni++) {
                    mma_bf16(acc[mi][ni], a[mi], bh[ni]);
                    mma_bf16(acc[mi][ni], a[mi], bl[ni]);
                }
#pragma unroll
            for (int mi = 0; mi < 4; mi++) ldsm4(a[mi], Abase + TILEB + aoff + mi * 16 * RSB);
#pragma unroll
            for (int mi = 0; mi < 4; mi++)
#pragma unroll
                for (int ni = 0; ni < 4; ni++)
                    mma_bf16(acc[mi][ni], a[mi], bh[ni]);
        }
        __syncthreads();
    }

    // ---- epilogue ----
    const int g4 = lane >> 2, t4 = lane & 3;
    const size_t HN_BASE = (size_t)NBATCH * SEQ * HID;
    float2 bias[4];
#pragma unroll
    for (int ni = 0; ni < 4; ni++)
        bias[ni] = *(const float2*)(Whb + j0 + warp_n * 32 + ni * 8 + t4 * 2);
#pragma unroll
    for (int mi = 0; mi < 4; mi++) {
        int ta = t0 + warp_m * 64 + mi * 16 + g4;
        int tb = ta + 8;
        size_t rowa = ((size_t)b * SEQ + ta) * HID;
        size_t rowb = ((size_t)b * SEQ + tb) * HID;
#pragma unroll
        for (int ni = 0; ni < 4; ni++) {
            int j = j0 + warp_n * 32 + ni * 8 + t4 * 2;
            float2 v0, v1;
            v0.x = fmaxf(acc[mi][ni][0] + bias[ni].x, 0.f);
            v0.y = fmaxf(acc[mi][ni][1] + bias[ni].y, 0.f);
            v1.x = fmaxf(acc[mi][ni][2] + bias[ni].x, 0.f);
            v1.y = fmaxf(acc[mi][ni][3] + bias[ni].y, 0.f);
            *(float2*)(out + rowa + j) = v0;
            *(float2*)(out + rowb + j) = v1;
            if (write_hn && tb == SEQ - 1)
                *(float2*)(out + HN_BASE + (size_t)b * HID + j) = v1;
        }
    }
}

// ---------------- launch ----------------
extern "C" void kernel_launch(void* const* d_in, const int* in_sizes, int n_in,
                              void* d_out, int out_size) {
    const float* x    = (const float*)d_in[0];
    const float* Wu_w = (const float*)d_in[1];
    const float* Wu_b = (const float*)d_in[2];
    const float* Wh_w = (const float*)d_in[3];
    const float* Wh_b = (const float*)d_in[4];
    const float* A    = (const float*)d_in[5];
    const float* B    = (const float*)d_in[6];
    float* out = (float*)d_out;

    int write_hn = (out_size >= NBATCH * SEQ * HID + NBATCH * HID) ? 1 : 0;

    static int smem_set = 0;
    if (!smem_set) {
        cudaFuncSetAttribute(k_main, cudaFuncAttributeMaxDynamicSharedMemorySize, SMEM_DYN);
        smem_set = 1;
    }

    k_u<<<NBATCH * SEQ / 8, 256>>>(x, Wu_w, Wu_b);
    k_pad<<<NBATCH, 128>>>();
    k_split_x<<<(NBATCH * SEQ * DIN) / 1024, 256>>>(x);
    k_wt<<<dim3(16, 16), 256>>>(Wh_w);
    k_init<<<MEM, 256>>>(A, B);
    int sel = 0;
    for (int n = 1; n <= 256; n <<= 1) {
        int blocks = 64 + ((n + 31) / 32) * 8;
        k_round<<<blocks, 256>>>(sel, n);
        sel ^= 1;
    }
    k_G<<<dim3(16, 16), 256>>>(Wh_w);
    k_main<<<dim3(HID / 128, SEQ / 128, NBATCH), 256, SMEM_DYN>>>(Wh_b, out, write_hn);
}

// round 5
// speedup vs baseline: 2.1401x; 1.0245x over previous
#include <cuda_runtime.h>
#include <cuda_bf16.h>
#include <cstdint>

#define SEQ 512
#define DIN 512
#define MEM 256
#define HID 512
#define NBATCH 64
#define URPAD 640

#define RSB 80                   // padded row stride bytes (40 bf16) for 32-col tiles
#define TILEB (128 * RSB)        // 10240 B per tile
#define BUFB (4 * TILEB)         // Ahi, Alo, Bhi, Blo
#define URS_OFF (2 * BUFB)       // smem offset of ur copy
#define SMEM_DYN (2 * BUFB + 2 * 1280)

// ---------------- static device scratch ----------------
__device__ __align__(16) __nv_bfloat16 g_xhi[NBATCH * SEQ * DIN];
__device__ __align__(16) __nv_bfloat16 g_xlo[NBATCH * SEQ * DIN];
__device__ __align__(16) __nv_bfloat16 g_urhi[NBATCH * URPAD];
__device__ __align__(16) __nv_bfloat16 g_urlo[NBATCH * URPAD];
__device__ __align__(16) __nv_bfloat16 g_whthi[HID * DIN];   // Wht[j][k] = Wh[256+k][j]
__device__ __align__(16) __nv_bfloat16 g_whtlo[HID * DIN];
__device__ __align__(16) __nv_bfloat16 g_gthi[HID * SEQ];    // Gt[j][d] = G[d][j]
__device__ __align__(16) __nv_bfloat16 g_gtlo[HID * SEQ];
__device__ float g_Ht[SEQ * MEM];
__device__ float g_AT[2][MEM * MEM];

// ---------------- helpers ----------------
__device__ __forceinline__ uint32_t smem_to_u32(const void* p) {
    uint32_t a;
    asm("{ .reg .u64 t; cvta.to.shared.u64 t, %1; cvt.u32.u64 %0, t; }" : "=r"(a) : "l"(p));
    return a;
}
__device__ __forceinline__ void cp16(uint32_t dst, const void* src) {
    asm volatile("cp.async.cg.shared.global [%0], [%1], 16;" :: "r"(dst), "l"(src));
}
#define CP_COMMIT() asm volatile("cp.async.commit_group;" ::: "memory")
#define CP_WAIT0()  asm volatile("cp.async.wait_group 0;" ::: "memory")
#define CP_WAIT1()  asm volatile("cp.async.wait_group 1;" ::: "memory")

__device__ __forceinline__ void ldsm4(uint32_t r[4], uint32_t addr) {
    asm volatile("ldmatrix.sync.aligned.m8n8.x4.shared.b16 {%0,%1,%2,%3}, [%4];"
                 : "=r"(r[0]), "=r"(r[1]), "=r"(r[2]), "=r"(r[3]) : "r"(addr));
}
__device__ __forceinline__ void mma_bf16(float* c, const uint32_t* a, const uint32_t* b) {
    asm volatile(
        "mma.sync.aligned.m16n8k16.row.col.f32.bf16.bf16.f32 "
        "{%0,%1,%2,%3}, {%4,%5,%6,%7}, {%8,%9}, {%0,%1,%2,%3};"
        : "+f"(c[0]), "+f"(c[1]), "+f"(c[2]), "+f"(c[3])
        : "r"(a[0]), "r"(a[1]), "r"(a[2]), "r"(a[3]), "r"(b[0]), "r"(b[1]));
}
__device__ __forceinline__ void split2(float v, __nv_bfloat16& h, __nv_bfloat16& l) {
    h = __float2bfloat16(v);
    l = __float2bfloat16(v - __bfloat162float(h));
}

// ---------------- k_ux: u = relu(x@Wu+b) + split x, one pass over x ----------------
__global__ __launch_bounds__(256) void k_ux(const float* __restrict__ x,
                                            const float* __restrict__ wu,
                                            const float* __restrict__ wub) {
    int row = blockIdx.x * 8 + (threadIdx.x >> 5);   // [0, 32768)
    int lane = threadIdx.x & 31;
    const float4* xr = (const float4*)(x + (size_t)row * DIN);
    const float4* wr = (const float4*)wu;
    float s = 0.f;
#pragma unroll
    for (int i = 0; i < 4; i++) {
        float4 v = xr[lane + 32 * i];
        float4 w = wr[lane + 32 * i];
        s += v.x * w.x + v.y * w.y + v.z * w.z + v.w * w.w;
        // split-write this quad
        __nv_bfloat16 h0, h1, h2, h3, l0, l1, l2, l3;
        split2(v.x, h0, l0); split2(v.y, h1, l1); split2(v.z, h2, l2); split2(v.w, h3, l3);
        size_t off = (size_t)row * DIN + (lane + 32 * i) * 4;
        __nv_bfloat162 ha = {h0, h1}, hb = {h2, h3}, la = {l0, l1}, lb = {l2, l3};
        *(__nv_bfloat162*)(g_xhi + off) = ha; *(__nv_bfloat162*)(g_xhi + off + 2) = hb;
        *(__nv_bfloat162*)(g_xlo + off) = la; *(__nv_bfloat162*)(g_xlo + off + 2) = lb;
    }
#pragma unroll
    for (int o = 16; o; o >>= 1) s += __shfl_xor_sync(0xffffffffu, s, o);
    if (lane == 0) {
        float u = fmaxf(s + wub[0], 0.f);
        int b = row >> 9, t = row & 511;
        __nv_bfloat16 h, l; split2(u, h, l);
        g_urhi[b * URPAD + (511 - t)] = h;
        g_urlo[b * URPAD + (511 - t)] = l;
    }
}

__global__ void k_pad() {
    int b = blockIdx.x, i = threadIdx.x;
    g_urhi[b * URPAD + 512 + i] = __float2bfloat16(0.f);
    g_urlo[b * URPAD + 512 + i] = __float2bfloat16(0.f);
}

// ---------------- k_wt: transpose+split Wh_x ----------------
__global__ __launch_bounds__(256) void k_wt(const float* __restrict__ Wh) {
    __shared__ float tile[32][33];
    int kb = blockIdx.x, jb = blockIdx.y;
    int tx = threadIdx.x & 31, ty = threadIdx.x >> 5;
    for (int yy = ty; yy < 32; yy += 8)
        tile[yy][tx] = Wh[(size_t)(MEM + kb * 32 + yy) * HID + jb * 32 + tx];
    __syncthreads();
    for (int yy = ty; yy < 32; yy += 8) {
        float v = tile[tx][yy];
        int j = jb * 32 + yy, k = kb * 32 + tx;
        __nv_bfloat16 h, l; split2(v, h, l);
        g_whthi[(size_t)j * DIN + k] = h;
        g_whtlo[(size_t)j * DIN + k] = l;
    }
}

// ---------------- k_init ----------------
__global__ __launch_bounds__(256) void k_init(const float* __restrict__ A,
                                              const float* __restrict__ B) {
    int k = blockIdx.x, m = threadIdx.x;
    g_AT[0][k * MEM + m] = A[m * MEM + k];
    if (k == 0) g_Ht[m] = B[m];
}

// ---------------- k_round: doubling (32x32 tiles); nsq = #squaring blocks ----------------
__global__ __launch_bounds__(256) void k_round(int sel, int n, int nsq) {
    __shared__ float As[16][32];
    __shared__ float Bs[16][33];
    const float* __restrict__ ATin = g_AT[sel];
    const float* Amat; float* Cmat; int rows;
    int bi = blockIdx.x;
    if (bi < nsq) { Amat = ATin; Cmat = g_AT[sel ^ 1]; rows = MEM; }
    else { bi -= nsq; Amat = g_Ht; Cmat = g_Ht + (size_t)n * MEM; rows = n; }
    int r0 = (bi >> 3) * 32, c0 = (bi & 7) * 32;
    int tid = threadIdx.x;
    int ar = tid >> 3, ac2 = (tid & 7) * 2;
    int bk = tid >> 4, bj2 = (tid & 15) * 2;
    int ty = tid >> 4, tx = tid & 15;
    float acc[2][2] = {};
    for (int k0 = 0; k0 < MEM; k0 += 16) {
        float2 av = make_float2(0.f, 0.f);
        if (r0 + ar < rows) av = *(const float2*)(Amat + (size_t)(r0 + ar) * MEM + k0 + ac2);
        float2 bv = *(const float2*)(ATin + (size_t)(k0 + bk) * MEM + c0 + bj2);
        __syncthreads();
        As[ac2][ar] = av.x; As[ac2 + 1][ar] = av.y;
        Bs[bk][bj2] = bv.x; Bs[bk][bj2 + 1] = bv.y;
        __syncthreads();
#pragma unroll
        for (int k = 0; k < 16; k++) {
            float a0 = As[k][ty * 2], a1 = As[k][ty * 2 + 1];
            float b0 = Bs[k][tx * 2], b1 = Bs[k][tx * 2 + 1];
            acc[0][0] = fmaf(a0, b0, acc[0][0]); acc[0][1] = fmaf(a0, b1, acc[0][1]);
            acc[1][0] = fmaf(a1, b0, acc[1][0]); acc[1][1] = fmaf(a1, b1, acc[1][1]);
        }
    }
#pragma unroll
    for (int i = 0; i < 2; i++) {
        int r = r0 + ty * 2 + i;
        if (r < rows) {
            Cmat[(size_t)r * MEM + c0 + tx * 2 + 0] = acc[i][0];
            Cmat[(size_t)r * MEM + c0 + tx * 2 + 1] = acc[i][1];
        }
    }
}

// ---------------- k_G: G=Ht@Wh_m -> transposed split gt ----------------
__global__ __launch_bounds__(256) void k_G(const float* __restrict__ Wh) {
    __shared__ float As[16][32];
    __shared__ float Bs[16][33];
    int r0 = blockIdx.y * 32, c0 = blockIdx.x * 32;
    int tid = threadIdx.x;
    int ar = tid >> 3, ac2 = (tid & 7) * 2;
    int bk = tid >> 4, bj2 = (tid & 15) * 2;
    int ty = tid >> 4, tx = tid & 15;
    float acc[2][2] = {};
    for (int k0 = 0; k0 < MEM; k0 += 16) {
        float2 av = *(const float2*)(g_Ht + (size_t)(r0 + ar) * MEM + k0 + ac2);
        float2 bv = *(const float2*)(Wh + (size_t)(k0 + bk) * HID + c0 + bj2);
        __syncthreads();
        As[ac2][ar] = av.x; As[ac2 + 1][ar] = av.y;
        Bs[bk][bj2] = bv.x; Bs[bk][bj2 + 1] = bv.y;
        __syncthreads();
#pragma unroll
        for (int k = 0; k < 16; k++) {
            float a0 = As[k][ty * 2], a1 = As[k][ty * 2 + 1];
            float b0 = Bs[k][tx * 2], b1 = Bs[k][tx * 2 + 1];
            acc[0][0] = fmaf(a0, b0, acc[0][0]); acc[0][1] = fmaf(a0, b1, acc[0][1]);
            acc[1][0] = fmaf(a1, b0, acc[1][0]); acc[1][1] = fmaf(a1, b1, acc[1][1]);
        }
    }
#pragma unroll
    for (int i = 0; i < 2; i++)
#pragma unroll
        for (int jj = 0; jj < 2; jj++) {
            int d = r0 + ty * 2 + i, j = c0 + tx * 2 + jj;
            __nv_bfloat16 h, l; split2(acc[i][jj], h, l);
            g_gthi[(size_t)j * SEQ + d] = h;
            g_gtlo[(size_t)j * SEQ + d] = l;
        }
}

// ---------------- k_main: mma.sync bf16 fused GEMM ----------------
__device__ __forceinline__ void cp_tile(uint32_t sdst, const __nv_bfloat16* __restrict__ g,
                                        int stride, int tid) {
#pragma unroll
    for (int it = 0; it < 2; it++) {
        int q = tid + it * 256;
        int row = q >> 2, ch = q & 3;
        cp16(sdst + row * RSB + ch * 16, g + (size_t)row * stride + ch * 8);
    }
}

__global__ __launch_bounds__(256, 2) void k_main(const float* __restrict__ Whb,
                                                 float* __restrict__ out, int write_hn) {
    extern __shared__ __align__(128) char smem[];
    const int b = blockIdx.z;
    const int t0 = blockIdx.y * 128;
    const int j0 = blockIdx.x * 128;
    const int tid = threadIdx.x;
    const int lane = tid & 31;
    const int warp_m = (tid >> 5) & 1;       // 2 warps in M
    const int warp_n = tid >> 6;             // 4 warps in N
    const uint32_t sbase = smem_to_u32(smem);

    // copy reversed u into smem (hi at URS_OFF, lo at +1280)
    {
        const uint32_t* gh = (const uint32_t*)(g_urhi + (size_t)b * URPAD);
        const uint32_t* gl = (const uint32_t*)(g_urlo + (size_t)b * URPAD);
        uint32_t* sh = (uint32_t*)(smem + URS_OFF);
        uint32_t* sl = (uint32_t*)(smem + URS_OFF + 1280);
        for (int q = tid; q < 320; q += 256) { sh[q] = gh[q]; sl[q] = gl[q]; }
    }
    __syncthreads();
    const uint32_t* ursh32 = (const uint32_t*)(smem + URS_OFF);
    const uint32_t* ursl32 = (const uint32_t*)(smem + URS_OFF + 1280);

    const __nv_bfloat16* xh = g_xhi + ((size_t)(b * SEQ + t0)) * DIN;
    const __nv_bfloat16* xl = g_xlo + ((size_t)(b * SEQ + t0)) * DIN;
    const __nv_bfloat16* wh = g_whthi + (size_t)j0 * DIN;
    const __nv_bfloat16* wl = g_whtlo + (size_t)j0 * DIN;
    const __nv_bfloat16* gh = g_gthi + (size_t)j0 * SEQ;
    const __nv_bfloat16* gl = g_gtlo + (size_t)j0 * SEQ;

    const int nchunks = 16 + 4 * (blockIdx.y + 1);

    auto fill = [&](int i, int p) {
        uint32_t sb = sbase + p * BUFB;
        char* sc = smem + p * BUFB;
        if (i < 16) {
            int k0 = i * 32;
            cp_tile(sb,              xh + k0, DIN, tid);
            cp_tile(sb + TILEB,      xl + k0, DIN, tid);
            cp_tile(sb + 2 * TILEB,  wh + k0, DIN, tid);
            cp_tile(sb + 3 * TILEB,  wl + k0, DIN, tid);
        } else {
            int d0 = (i - 16) * 32;
            cp_tile(sb + 2 * TILEB,  gh + d0, SEQ, tid);
            cp_tile(sb + 3 * TILEB,  gl + d0, SEQ, tid);
            int r = tid >> 1, half = tid & 1;
            int s0 = 511 - (t0 + r) + d0 + half * 16;
            int base = s0 >> 1, par = s0 & 1;
            uint32_t w[8];
            uint32_t w0 = ursh32[base];
#pragma unroll
            for (int c = 0; c < 8; c++) {
                uint32_t w1 = ursh32[base + c + 1];
                w[c] = par ? __byte_perm(w0, w1, 0x5432) : w0;
                w0 = w1;
            }
            *(uint4*)(sc + r * RSB + half * 32)      = make_uint4(w[0], w[1], w[2], w[3]);
            *(uint4*)(sc + r * RSB + half * 32 + 16) = make_uint4(w[4], w[5], w[6], w[7]);
            w0 = ursl32[base];
#pragma unroll
            for (int c = 0; c < 8; c++) {
                uint32_t w1 = ursl32[base + c + 1];
                w[c] = par ? __byte_perm(w0, w1, 0x5432) : w0;
                w0 = w1;
            }
            *(uint4*)(sc + TILEB + r * RSB + half * 32)      = make_uint4(w[0], w[1], w[2], w[3]);
            *(uint4*)(sc + TILEB + r * RSB + half * 32 + 16) = make_uint4(w[4], w[5], w[6], w[7]);
        }
    };

    float acc[4][4][4];
#pragma unroll
    for (int mi = 0; mi < 4; mi++)
#pragma unroll
        for (int ni = 0; ni < 4; ni++)
#pragma unroll
            for (int e = 0; e < 4; e++) acc[mi][ni][e] = 0.f;

    fill(0, 0);
    CP_COMMIT();

    for (int i = 0; i < nchunks; i++) {
        int p = i & 1;
        if (i + 1 < nchunks) { fill(i + 1, p ^ 1); CP_COMMIT(); CP_WAIT1(); }
        else CP_WAIT0();
        __syncthreads();

        uint32_t Abase = sbase + p * BUFB;
        uint32_t Bbase = Abase + 2 * TILEB;
#pragma unroll
        for (int ks = 0; ks < 2; ks++) {
            uint32_t bh[4][2], bl[4][2];
#pragma unroll
            for (int np = 0; np < 2; np++) {
                uint32_t r[4];
                uint32_t baddr = Bbase +
                    (warp_n * 32 + np * 16 + (lane & 15)) * RSB +
                    ks * 32 + ((lane >> 4) << 4);
                ldsm4(r, baddr);
                bh[np * 2][0] = r[0];     bh[np * 2][1] = r[2];
                bh[np * 2 + 1][0] = r[1]; bh[np * 2 + 1][1] = r[3];
                ldsm4(r, baddr + TILEB);
                bl[np * 2][0] = r[0];     bl[np * 2][1] = r[2];
                bl[np * 2 + 1][0] = r[1]; bl[np * 2 + 1][1] = r[3];
            }
            uint32_t a[4][4];
            uint32_t aoff = (warp_m * 64 + (lane & 15)) * RSB + ks * 32 + ((lane >> 4) << 4);
#pragma unroll
            for (int mi = 0; mi < 4; mi++) ldsm4(a[mi], Abase + aoff + mi * 16 * RSB);
#pragma unroll
            for (int mi = 0; mi < 4; mi++)
#pragma unroll
                for (int ni = 0; ni < 4; ni++) {
                    mma_bf16(acc[mi][ni], a[mi], bh[ni]);
                    mma_bf16(acc[mi][ni], a[mi], bl[ni]);
                }
#pragma unroll
            for (int mi = 0; mi < 4; mi++) ldsm4(a[mi], Abase + TILEB + aoff + mi * 16 * RSB);
#pragma unroll
            for (int mi = 0; mi < 4; mi++)
#pragma unroll
                for (int ni = 0; ni < 4; ni++)
                    mma_bf16(acc[mi][ni], a[mi], bh[ni]);
        }
        __syncthreads();
    }

    // ---- epilogue ----
    const int g4 = lane >> 2, t4 = lane & 3;
    const size_t HN_BASE = (size_t)NBATCH * SEQ * HID;
    float2 bias[4];
#pragma unroll
    for (int ni = 0; ni < 4; ni++)
        bias[ni] = *(const float2*)(Whb + j0 + warp_n * 32 + ni * 8 + t4 * 2);
#pragma unroll
    for (int mi = 0; mi < 4; mi++) {
        int ta = t0 + warp_m * 64 + mi * 16 + g4;
        int tb = ta + 8;
        size_t rowa = ((size_t)b * SEQ + ta) * HID;
        size_t rowb = ((size_t)b * SEQ + tb) * HID;
#pragma unroll
        for (int ni = 0; ni < 4; ni++) {
            int j = j0 + warp_n * 32 + ni * 8 + t4 * 2;
            float2 v0, v1;
            v0.x = fmaxf(acc[mi][ni][0] + bias[ni].x, 0.f);
            v0.y = fmaxf(acc[mi][ni][1] + bias[ni].y, 0.f);
            v1.x = fmaxf(acc[mi][ni][2] + bias[ni].x, 0.f);
            v1.y = fmaxf(acc[mi][ni][3] + bias[ni].y, 0.f);
            *(float2*)(out + rowa + j) = v0;
            *(float2*)(out + rowb + j) = v1;
            if (write_hn && tb == SEQ - 1)
                *(float2*)(out + HN_BASE + (size_t)b * HID + j) = v1;
        }
    }
}

// ---------------- launch ----------------
extern "C" void kernel_launch(void* const* d_in, const int* in_sizes, int n_in,
                              void* d_out, int out_size) {
    const float* x    = (const float*)d_in[0];
    const float* Wu_w = (const float*)d_in[1];
    const float* Wu_b = (const float*)d_in[2];
    const float* Wh_w = (const float*)d_in[3];
    const float* Wh_b = (const float*)d_in[4];
    const float* A    = (const float*)d_in[5];
    const float* B    = (const float*)d_in[6];
    float* out = (float*)d_out;

    int write_hn = (out_size >= NBATCH * SEQ * HID + NBATCH * HID) ? 1 : 0;

    static int smem_set = 0;
    if (!smem_set) {
        cudaFuncSetAttribute(k_main, cudaFuncAttributeMaxDynamicSharedMemorySize, SMEM_DYN);
        smem_set = 1;
    }

    k_ux<<<NBATCH * SEQ / 8, 256>>>(x, Wu_w, Wu_b);
    k_pad<<<NBATCH, 128>>>();
    k_wt<<<dim3(16, 16), 256>>>(Wh_w);
    k_init<<<MEM, 256>>>(A, B);
    int sel = 0;
    for (int n = 1; n <= 256; n <<= 1) {
        int nsq = (n == 256) ? 0 : 64;           // skip final squaring (A^512 unused)
        int blocks = nsq + ((n + 31) / 32) * 8;
        k_round<<<blocks, 256>>>(sel, n, nsq);
        sel ^= 1;
    }
    // NOTE: after the loop, g_Ht is complete; g_AT parity doesn't matter.
    k_G<<<dim3(16, 16), 256>>>(Wh_w);
    k_main<<<dim3(HID / 128, SEQ / 128, NBATCH), 256, SMEM_DYN>>>(Wh_b, out, write_hn);
}

// round 6
// speedup vs baseline: 2.8868x; 1.3489x over previous
#include <cuda_runtime.h>
#include <cuda_fp16.h>
#include <cstdint>

#define SEQ 512
#define DIN 512
#define MEM 256
#define HID 512
#define NBATCH 64
#define URPAD 640

#define RSB 144                  // row stride bytes: 64 fp16 = 128 B + 16 pad
#define TILEB (128 * RSB)        // 18432 B
#define BUFB (3 * TILEB)         // A_hi, A_lo, B
#define URS_OFF (2 * BUFB)
#define SMEM_DYN (2 * BUFB + 2 * 1280)

// ---------------- static device scratch ----------------
__device__ __align__(16) __half g_xhi[NBATCH * SEQ * DIN];
__device__ __align__(16) __half g_xlo[NBATCH * SEQ * DIN];
__device__ __align__(16) __half g_urhi[NBATCH * URPAD];
__device__ __align__(16) __half g_urlo[NBATCH * URPAD];
__device__ __align__(16) __half g_wht[HID * DIN];    // Wht[j][k] = Wh[256+k][j]
__device__ __align__(16) __half g_gt[HID * SEQ];     // Gt[j][d] = G[d][j]
__device__ float g_Ht[SEQ * MEM];
__device__ float g_AT[2][MEM * MEM];

// ---------------- helpers ----------------
__device__ __forceinline__ uint32_t smem_to_u32(const void* p) {
    uint32_t a;
    asm("{ .reg .u64 t; cvta.to.shared.u64 t, %1; cvt.u32.u64 %0, t; }" : "=r"(a) : "l"(p));
    return a;
}
__device__ __forceinline__ void cp16(uint32_t dst, const void* src) {
    asm volatile("cp.async.cg.shared.global [%0], [%1], 16;" :: "r"(dst), "l"(src));
}
#define CP_COMMIT() asm volatile("cp.async.commit_group;" ::: "memory")
#define CP_WAIT0()  asm volatile("cp.async.wait_group 0;" ::: "memory")
#define CP_WAIT1()  asm volatile("cp.async.wait_group 1;" ::: "memory")

__device__ __forceinline__ void ldsm4(uint32_t r[4], uint32_t addr) {
    asm volatile("ldmatrix.sync.aligned.m8n8.x4.shared.b16 {%0,%1,%2,%3}, [%4];"
                 : "=r"(r[0]), "=r"(r[1]), "=r"(r[2]), "=r"(r[3]) : "r"(addr));
}
__device__ __forceinline__ void mma_f16(float* c, const uint32_t* a, const uint32_t* b) {
    asm volatile(
        "mma.sync.aligned.m16n8k16.row.col.f32.f16.f16.f32 "
        "{%0,%1,%2,%3}, {%4,%5,%6,%7}, {%8,%9}, {%0,%1,%2,%3};"
        : "+f"(c[0]), "+f"(c[1]), "+f"(c[2]), "+f"(c[3])
        : "r"(a[0]), "r"(a[1]), "r"(a[2]), "r"(a[3]), "r"(b[0]), "r"(b[1]));
}
__device__ __forceinline__ void split2h(float v, __half& h, __half& l) {
    h = __float2half(v);
    l = __float2half(v - __half2float(h));
}

// ---------------- k_ux: u + split x + pad, one pass over x ----------------
__global__ __launch_bounds__(256) void k_ux(const float* __restrict__ x,
                                            const float* __restrict__ wu,
                                            const float* __restrict__ wub) {
    int row = blockIdx.x * 8 + (threadIdx.x >> 5);   // [0, 32768)
    int lane = threadIdx.x & 31;
    const float4* xr = (const float4*)(x + (size_t)row * DIN);
    const float4* wr = (const float4*)wu;
    float s = 0.f;
#pragma unroll
    for (int i = 0; i < 4; i++) {
        float4 v = xr[lane + 32 * i];
        float4 w = wr[lane + 32 * i];
        s += v.x * w.x + v.y * w.y + v.z * w.z + v.w * w.w;
        __half h0, h1, h2, h3, l0, l1, l2, l3;
        split2h(v.x, h0, l0); split2h(v.y, h1, l1); split2h(v.z, h2, l2); split2h(v.w, h3, l3);
        size_t off = (size_t)row * DIN + (lane + 32 * i) * 4;
        __half2 ha = {h0, h1}, hb = {h2, h3}, la = {l0, l1}, lb = {l2, l3};
        *(__half2*)(g_xhi + off) = ha; *(__half2*)(g_xhi + off + 2) = hb;
        *(__half2*)(g_xlo + off) = la; *(__half2*)(g_xlo + off + 2) = lb;
    }
#pragma unroll
    for (int o = 16; o; o >>= 1) s += __shfl_xor_sync(0xffffffffu, s, o);
    if (lane == 0) {
        float u = fmaxf(s + wub[0], 0.f);
        int b = row >> 9, t = row & 511;
        __half h, l; split2h(u, h, l);
        g_urhi[b * URPAD + (511 - t)] = h;
        g_urlo[b * URPAD + (511 - t)] = l;
        if (t < 128) {   // zero pad region [512, 640)
            g_urhi[b * URPAD + 512 + t] = __float2half(0.f);
            g_urlo[b * URPAD + 512 + t] = __float2half(0.f);
        }
    }
}

// ---------------- k_wt: transpose Wh_x -> fp16; also A^T init + Ht[0]=B ----------------
__global__ __launch_bounds__(256) void k_wt(const float* __restrict__ Wh,
                                            const float* __restrict__ A,
                                            const float* __restrict__ Bv) {
    __shared__ float tile[32][33];
    int kb = blockIdx.x, jb = blockIdx.y;
    int bid = jb * 16 + kb;                       // [0,256)
    // init chain state
    g_AT[0][bid * MEM + threadIdx.x] = A[(size_t)threadIdx.x * MEM + bid];
    if (bid == 0) g_Ht[threadIdx.x] = Bv[threadIdx.x];

    int tx = threadIdx.x & 31, ty = threadIdx.x >> 5;
    for (int yy = ty; yy < 32; yy += 8)
        tile[yy][tx] = Wh[(size_t)(MEM + kb * 32 + yy) * HID + jb * 32 + tx];
    __syncthreads();
    for (int yy = ty; yy < 32; yy += 8) {
        float v = tile[tx][yy];
        int j = jb * 32 + yy, k = kb * 32 + tx;
        g_wht[(size_t)j * DIN + k] = __float2half(v);
    }
}

// ---------------- k_round: doubling (32x32 tiles); nsq = #squaring blocks ----------------
__global__ __launch_bounds__(256) void k_round(int sel, int n, int nsq) {
    __shared__ float As[16][32];
    __shared__ float Bs[16][33];
    const float* __restrict__ ATin = g_AT[sel];
    const float* Amat; float* Cmat; int rows;
    int bi = blockIdx.x;
    if (bi < nsq) { Amat = ATin; Cmat = g_AT[sel ^ 1]; rows = MEM; }
    else { bi -= nsq; Amat = g_Ht; Cmat = g_Ht + (size_t)n * MEM; rows = n; }
    int r0 = (bi >> 3) * 32, c0 = (bi & 7) * 32;
    int tid = threadIdx.x;
    int ar = tid >> 3, ac2 = (tid & 7) * 2;
    int bk = tid >> 4, bj2 = (tid & 15) * 2;
    int ty = tid >> 4, tx = tid & 15;
    float acc[2][2] = {};
    for (int k0 = 0; k0 < MEM; k0 += 16) {
        float2 av = make_float2(0.f, 0.f);
        if (r0 + ar < rows) av = *(const float2*)(Amat + (size_t)(r0 + ar) * MEM + k0 + ac2);
        float2 bv = *(const float2*)(ATin + (size_t)(k0 + bk) * MEM + c0 + bj2);
        __syncthreads();
        As[ac2][ar] = av.x; As[ac2 + 1][ar] = av.y;
        Bs[bk][bj2] = bv.x; Bs[bk][bj2 + 1] = bv.y;
        __syncthreads();
#pragma unroll
        for (int k = 0; k < 16; k++) {
            float a0 = As[k][ty * 2], a1 = As[k][ty * 2 + 1];
            float b0 = Bs[k][tx * 2], b1 = Bs[k][tx * 2 + 1];
            acc[0][0] = fmaf(a0, b0, acc[0][0]); acc[0][1] = fmaf(a0, b1, acc[0][1]);
            acc[1][0] = fmaf(a1, b0, acc[1][0]); acc[1][1] = fmaf(a1, b1, acc[1][1]);
        }
    }
#pragma unroll
    for (int i = 0; i < 2; i++) {
        int r = r0 + ty * 2 + i;
        if (r < rows) {
            Cmat[(size_t)r * MEM + c0 + tx * 2 + 0] = acc[i][0];
            Cmat[(size_t)r * MEM + c0 + tx * 2 + 1] = acc[i][1];
        }
    }
}

// ---------------- k_G: G=Ht@Wh_m -> transposed fp16 gt ----------------
__global__ __launch_bounds__(256) void k_G(const float* __restrict__ Wh) {
    __shared__ float As[16][32];
    __shared__ float Bs[16][33];
    int r0 = blockIdx.y * 32, c0 = blockIdx.x * 32;   // r=d, c=j
    int tid = threadIdx.x;
    int ar = tid >> 3, ac2 = (tid & 7) * 2;
    int bk = tid >> 4, bj2 = (tid & 15) * 2;
    int ty = tid >> 4, tx = tid & 15;
    float acc[2][2] = {};
    for (int k0 = 0; k0 < MEM; k0 += 16) {
        float2 av = *(const float2*)(g_Ht + (size_t)(r0 + ar) * MEM + k0 + ac2);
        float2 bv = *(const float2*)(Wh + (size_t)(k0 + bk) * HID + c0 + bj2);
        __syncthreads();
        As[ac2][ar] = av.x; As[ac2 + 1][ar] = av.y;
        Bs[bk][bj2] = bv.x; Bs[bk][bj2 + 1] = bv.y;
        __syncthreads();
#pragma unroll
        for (int k = 0; k < 16; k++) {
            float a0 = As[k][ty * 2], a1 = As[k][ty * 2 + 1];
            float b0 = Bs[k][tx * 2], b1 = Bs[k][tx * 2 + 1];
            acc[0][0] = fmaf(a0, b0, acc[0][0]); acc[0][1] = fmaf(a0, b1, acc[0][1]);
            acc[1][0] = fmaf(a1, b0, acc[1][0]); acc[1][1] = fmaf(a1, b1, acc[1][1]);
        }
    }
#pragma unroll
    for (int i = 0; i < 2; i++)
#pragma unroll
        for (int jj = 0; jj < 2; jj++) {
            int d = r0 + ty * 2 + i, j = c0 + tx * 2 + jj;
            g_gt[(size_t)j * SEQ + d] = __float2half(acc[i][jj]);
        }
}

// ---------------- k_main: fp16 2-product fused GEMM, K=64 chunks ----------------
__device__ __forceinline__ void cp_tile64(uint32_t sdst, const __half* __restrict__ g,
                                          int stride, int tid) {
#pragma unroll
    for (int it = 0; it < 4; it++) {
        int q = tid + it * 256;            // [0,1024)
        int row = q >> 3, ch = q & 7;      // 128 rows x 8 x 16B
        cp16(sdst + row * RSB + ch * 16, g + (size_t)row * stride + ch * 8);
    }
}

__global__ __launch_bounds__(256, 2) void k_main(const float* __restrict__ Whb,
                                                 float* __restrict__ out, int write_hn) {
    extern __shared__ __align__(128) char smem[];
    const int b = blockIdx.z;
    const int t0 = blockIdx.y * 128;
    const int j0 = blockIdx.x * 128;
    const int tid = threadIdx.x;
    const int lane = tid & 31;
    const int warp_m = (tid >> 5) & 1;
    const int warp_n = tid >> 6;
    const uint32_t sbase = smem_to_u32(smem);

    // copy reversed u (fp16 hi/lo) into smem
    {
        const uint32_t* gh = (const uint32_t*)(g_urhi + (size_t)b * URPAD);
        const uint32_t* gl = (const uint32_t*)(g_urlo + (size_t)b * URPAD);
        uint32_t* sh = (uint32_t*)(smem + URS_OFF);
        uint32_t* sl = (uint32_t*)(smem + URS_OFF + 1280);
        for (int q = tid; q < 320; q += 256) { sh[q] = gh[q]; sl[q] = gl[q]; }
    }
    __syncthreads();
    const uint32_t* ursh32 = (const uint32_t*)(smem + URS_OFF);
    const uint32_t* ursl32 = (const uint32_t*)(smem + URS_OFF + 1280);

    const __half* xh = g_xhi + ((size_t)(b * SEQ + t0)) * DIN;
    const __half* xl = g_xlo + ((size_t)(b * SEQ + t0)) * DIN;
    const __half* wt = g_wht + (size_t)j0 * DIN;
    const __half* gt = g_gt + (size_t)j0 * SEQ;

    const int nchunks = 10 + 2 * blockIdx.y;   // 8 dense + (2*by+2) toeplitz

    auto fill = [&](int i, int p) {
        uint32_t sb = sbase + p * BUFB;
        char* sc = smem + p * BUFB;
        if (i < 8) {
            int k0 = i * 64;
            cp_tile64(sb,             xh + k0, DIN, tid);
            cp_tile64(sb + TILEB,     xl + k0, DIN, tid);
            cp_tile64(sb + 2 * TILEB, wt + k0, DIN, tid);
        } else {
            int d0 = (i - 8) * 64;
            cp_tile64(sb + 2 * TILEB, gt + d0, SEQ, tid);
            // Toeplitz A synth: row r, each of 2 threads covers 32 fp16 (64 B)
            int r = tid >> 1, hf = tid & 1;
            int s0 = 511 - (t0 + r) + d0 + hf * 32;
            int base = s0 >> 1, par = s0 & 1;
            uint32_t w[16];
            uint32_t w0 = ursh32[base];
#pragma unroll
            for (int c = 0; c < 16; c++) {
                uint32_t w1 = ursh32[base + c + 1];
                w[c] = par ? __byte_perm(w0, w1, 0x5432) : w0;
                w0 = w1;
            }
#pragma unroll
            for (int q = 0; q < 4; q++)
                *(uint4*)(sc + r * RSB + hf * 64 + q * 16) =
                    make_uint4(w[q * 4], w[q * 4 + 1], w[q * 4 + 2], w[q * 4 + 3]);
            w0 = ursl32[base];
#pragma unroll
            for (int c = 0; c < 16; c++) {
                uint32_t w1 = ursl32[base + c + 1];
                w[c] = par ? __byte_perm(w0, w1, 0x5432) : w0;
                w0 = w1;
            }
#pragma unroll
            for (int q = 0; q < 4; q++)
                *(uint4*)(sc + TILEB + r * RSB + hf * 64 + q * 16) =
                    make_uint4(w[q * 4], w[q * 4 + 1], w[q * 4 + 2], w[q * 4 + 3]);
        }
    };

    float acc[4][4][4];
#pragma unroll
    for (int mi = 0; mi < 4; mi++)
#pragma unroll
        for (int ni = 0; ni < 4; ni++)
#pragma unroll
            for (int e = 0; e < 4; e++) acc[mi][ni][e] = 0.f;

    fill(0, 0);
    CP_COMMIT();

    for (int i = 0; i < nchunks; i++) {
        int p = i & 1;
        if (i + 1 < nchunks) { fill(i + 1, p ^ 1); CP_COMMIT(); CP_WAIT1(); }
        else CP_WAIT0();
        __syncthreads();

        uint32_t Abase = sbase + p * BUFB;
        uint32_t Bbase = Abase + 2 * TILEB;
#pragma unroll
        for (int ks = 0; ks < 4; ks++) {
            uint32_t bh[4][2];
#pragma unroll
            for (int np = 0; np < 2; np++) {
                uint32_t r[4];
                uint32_t baddr = Bbase +
                    (warp_n * 32 + np * 16 + (lane & 15)) * RSB +
                    ks * 32 + ((lane >> 4) << 4);
                ldsm4(r, baddr);
                bh[np * 2][0] = r[0];     bh[np * 2][1] = r[2];
                bh[np * 2 + 1][0] = r[1]; bh[np * 2 + 1][1] = r[3];
            }
            uint32_t a[4][4];
            uint32_t aoff = (warp_m * 64 + (lane & 15)) * RSB + ks * 32 + ((lane >> 4) << 4);
#pragma unroll
            for (int mi = 0; mi < 4; mi++) ldsm4(a[mi], Abase + aoff + mi * 16 * RSB);
#pragma unroll
            for (int mi = 0; mi < 4; mi++)
#pragma unroll
                for (int ni = 0; ni < 4; ni++)
                    mma_f16(acc[mi][ni], a[mi], bh[ni]);
#pragma unroll
            for (int mi = 0; mi < 4; mi++) ldsm4(a[mi], Abase + TILEB + aoff + mi * 16 * RSB);
#pragma unroll
            for (int mi = 0; mi < 4; mi++)
#pragma unroll
                for (int ni = 0; ni < 4; ni++)
                    mma_f16(acc[mi][ni], a[mi], bh[ni]);
        }
        __syncthreads();
    }

    // ---- epilogue ----
    const int g4 = lane >> 2, t4 = lane & 3;
    const size_t HN_BASE = (size_t)NBATCH * SEQ * HID;
    float2 bias[4];
#pragma unroll
    for (int ni = 0; ni < 4; ni++)
        bias[ni] = *(const float2*)(Whb + j0 + warp_n * 32 + ni * 8 + t4 * 2);
#pragma unroll
    for (int mi = 0; mi < 4; mi++) {
        int ta = t0 + warp_m * 64 + mi * 16 + g4;
        int tb = ta + 8;
        size_t rowa = ((size_t)b * SEQ + ta) * HID;
        size_t rowb = ((size_t)b * SEQ + tb) * HID;
#pragma unroll
        for (int ni = 0; ni < 4; ni++) {
            int j = j0 + warp_n * 32 + ni * 8 + t4 * 2;
            float2 v0, v1;
            v0.x = fmaxf(acc[mi][ni][0] + bias[ni].x, 0.f);
            v0.y = fmaxf(acc[mi][ni][1] + bias[ni].y, 0.f);
            v1.x = fmaxf(acc[mi][ni][2] + bias[ni].x, 0.f);
            v1.y = fmaxf(acc[mi][ni][3] + bias[ni].y, 0.f);
            *(float2*)(out + rowa + j) = v0;
            *(float2*)(out + rowb + j) = v1;
            if (write_hn && tb == SEQ - 1)
                *(float2*)(out + HN_BASE + (size_t)b * HID + j) = v1;
        }
    }
}

// ---------------- launch ----------------
extern "C" void kernel_launch(void* const* d_in, const int* in_sizes, int n_in,
                              void* d_out, int out_size) {
    const float* x    = (const float*)d_in[0];
    const float* Wu_w = (const float*)d_in[1];
    const float* Wu_b = (const float*)d_in[2];
    const float* Wh_w = (const float*)d_in[3];
    const float* Wh_b = (const float*)d_in[4];
    const float* A    = (const float*)d_in[5];
    const float* B    = (const float*)d_in[6];
    float* out = (float*)d_out;

    int write_hn = (out_size >= NBATCH * SEQ * HID + NBATCH * HID) ? 1 : 0;

    static int smem_set = 0;
    if (!smem_set) {
        cudaFuncSetAttribute(k_main, cudaFuncAttributeMaxDynamicSharedMemorySize, SMEM_DYN);
        smem_set = 1;
    }

    k_ux<<<NBATCH * SEQ / 8, 256>>>(x, Wu_w, Wu_b);
    k_wt<<<dim3(16, 16), 256>>>(Wh_w, A, B);
    int sel = 0;
    for (int n = 1; n <= 256; n <<= 1) {
        int nsq = (n == 256) ? 0 : 64;           // skip final squaring (A^512 unused)
        int blocks = nsq + ((n + 31) / 32) * 8;
        k_round<<<blocks, 256>>>(sel, n, nsq);
        sel ^= 1;
    }
    k_G<<<dim3(16, 16), 256>>>(Wh_w);
    k_main<<<dim3(HID / 128, SEQ / 128, NBATCH), 256, SMEM_DYN>>>(Wh_b, out, write_hn);
}

// round 7
// speedup vs baseline: 3.1120x; 1.0780x over previous
#include <cuda_runtime.h>
#include <cuda_fp16.h>
#include <cstdint>

#define SEQ 512
#define DIN 512
#define MEM 256
#define HID 512
#define NBATCH 64
#define URPAD 640

#define RSB 144                  // row stride bytes: 64 fp16 = 128 B + 16 pad
#define TILEB (128 * RSB)        // 18432 B
#define BUFB (3 * TILEB)         // A_hi, A_lo, B
#define URS_OFF (2 * BUFB)
#define SMEM_DYN (2 * BUFB + 2 * 1280)

// ---------------- static device scratch ----------------
__device__ __align__(16) __half g_xhi[NBATCH * SEQ * DIN];
__device__ __align__(16) __half g_xlo[NBATCH * SEQ * DIN];
__device__ __align__(16) __half g_urhi[NBATCH * URPAD];
__device__ __align__(16) __half g_urlo[NBATCH * URPAD];
__device__ __align__(16) __half g_wht[HID * DIN];    // Wht[j][k] = Wh[256+k][j]
__device__ __align__(16) __half g_gt[HID * SEQ];     // Gt[j][d] = G[d][j]
__device__ float g_Ht[SEQ * MEM];
__device__ float g_AT[2][MEM * MEM];

// ---------------- helpers ----------------
__device__ __forceinline__ uint32_t smem_to_u32(const void* p) {
    uint32_t a;
    asm("{ .reg .u64 t; cvta.to.shared.u64 t, %1; cvt.u32.u64 %0, t; }" : "=r"(a) : "l"(p));
    return a;
}
__device__ __forceinline__ void cp16(uint32_t dst, const void* src) {
    asm volatile("cp.async.cg.shared.global [%0], [%1], 16;" :: "r"(dst), "l"(src));
}
#define CP_COMMIT() asm volatile("cp.async.commit_group;" ::: "memory")
#define CP_WAIT0()  asm volatile("cp.async.wait_group 0;" ::: "memory")
#define CP_WAIT1()  asm volatile("cp.async.wait_group 1;" ::: "memory")

__device__ __forceinline__ void ldsm4(uint32_t r[4], uint32_t addr) {
    asm volatile("ldmatrix.sync.aligned.m8n8.x4.shared.b16 {%0,%1,%2,%3}, [%4];"
                 : "=r"(r[0]), "=r"(r[1]), "=r"(r[2]), "=r"(r[3]) : "r"(addr));
}
__device__ __forceinline__ void mma_f16(float* c, const uint32_t* a, const uint32_t* b) {
    asm volatile(
        "mma.sync.aligned.m16n8k16.row.col.f32.f16.f16.f32 "
        "{%0,%1,%2,%3}, {%4,%5,%6,%7}, {%8,%9}, {%0,%1,%2,%3};"
        : "+f"(c[0]), "+f"(c[1]), "+f"(c[2]), "+f"(c[3])
        : "r"(a[0]), "r"(a[1]), "r"(a[2]), "r"(a[3]), "r"(b[0]), "r"(b[1]));
}
__device__ __forceinline__ void split2h(float v, __half& h, __half& l) {
    h = __float2half(v);
    l = __float2half(v - __half2float(h));
}

// ---------------- k_ux: u + split x + pad, one pass over x ----------------
__global__ __launch_bounds__(256) void k_ux(const float* __restrict__ x,
                                            const float* __restrict__ wu,
                                            const float* __restrict__ wub) {
    int row = blockIdx.x * 8 + (threadIdx.x >> 5);   // [0, 32768)
    int lane = threadIdx.x & 31;
    const float4* xr = (const float4*)(x + (size_t)row * DIN);
    const float4* wr = (const float4*)wu;
    float s = 0.f;
#pragma unroll
    for (int i = 0; i < 4; i++) {
        float4 v = xr[lane + 32 * i];
        float4 w = wr[lane + 32 * i];
        s += v.x * w.x + v.y * w.y + v.z * w.z + v.w * w.w;
        __half h0, h1, h2, h3, l0, l1, l2, l3;
        split2h(v.x, h0, l0); split2h(v.y, h1, l1); split2h(v.z, h2, l2); split2h(v.w, h3, l3);
        size_t off = (size_t)row * DIN + (lane + 32 * i) * 4;
        __half2 ha = {h0, h1}, hb = {h2, h3}, la = {l0, l1}, lb = {l2, l3};
        *(__half2*)(g_xhi + off) = ha; *(__half2*)(g_xhi + off + 2) = hb;
        *(__half2*)(g_xlo + off) = la; *(__half2*)(g_xlo + off + 2) = lb;
    }
#pragma unroll
    for (int o = 16; o; o >>= 1) s += __shfl_xor_sync(0xffffffffu, s, o);
    if (lane == 0) {
        float u = fmaxf(s + wub[0], 0.f);
        int b = row >> 9, t = row & 511;
        __half h, l; split2h(u, h, l);
        g_urhi[b * URPAD + (511 - t)] = h;
        g_urlo[b * URPAD + (511 - t)] = l;
        if (t < 128) {   // zero pad region [512, 640)
            g_urhi[b * URPAD + 512 + t] = __float2half(0.f);
            g_urlo[b * URPAD + 512 + t] = __float2half(0.f);
        }
    }
}

// ---------------- k_wt: transpose Wh_x -> fp16; also A^T init + Ht[0]=B ----------------
__global__ __launch_bounds__(256) void k_wt(const float* __restrict__ Wh,
                                            const float* __restrict__ A,
                                            const float* __restrict__ Bv) {
    __shared__ float tile[32][33];
    int kb = blockIdx.x, jb = blockIdx.y;
    int bid = jb * 16 + kb;                       // [0,256)
    g_AT[0][bid * MEM + threadIdx.x] = A[(size_t)threadIdx.x * MEM + bid];
    if (bid == 0) g_Ht[threadIdx.x] = Bv[threadIdx.x];

    int tx = threadIdx.x & 31, ty = threadIdx.x >> 5;
    for (int yy = ty; yy < 32; yy += 8)
        tile[yy][tx] = Wh[(size_t)(MEM + kb * 32 + yy) * HID + jb * 32 + tx];
    __syncthreads();
    for (int yy = ty; yy < 32; yy += 8) {
        float v = tile[tx][yy];
        int j = jb * 32 + yy, k = kb * 32 + tx;
        g_wht[(size_t)j * DIN + k] = __float2half(v);
    }
}

// ---------------- k_round2: doubling round, 16x16 tiles (1 out/thread) ----------------
// blocks [0,nsq): square (A^n)^T -> (A^2n)^T; blocks [nsq,...): Ht[n+d] = Ht[d] @ ATn
__global__ __launch_bounds__(256) void k_round2(int sel, int n, int nsq) {
    __shared__ float Xs[16][16];
    __shared__ float Bs[16][16];
    const float* __restrict__ ATin = g_AT[sel];
    const float* Amat; float* Cmat; int rows;
    int bi = blockIdx.x;
    if (bi < nsq) { Amat = ATin; Cmat = g_AT[sel ^ 1]; rows = MEM; }
    else { bi -= nsq; Amat = g_Ht; Cmat = g_Ht + (size_t)n * MEM; rows = n; }
    int r0 = (bi >> 4) * 16, c0 = (bi & 15) * 16;
    int ty = threadIdx.x >> 4, tx = threadIdx.x & 15;
    int rowOk = (r0 + ty < rows);
    float acc = 0.f;
    float xv = rowOk ? Amat[(size_t)(r0 + ty) * MEM + tx] : 0.f;
    float bv = ATin[(size_t)ty * MEM + c0 + tx];
    for (int k0 = 0; k0 < MEM; k0 += 16) {
        __syncthreads();
        Xs[ty][tx] = xv; Bs[ty][tx] = bv;
        __syncthreads();
        if (k0 + 16 < MEM) {
            xv = rowOk ? Amat[(size_t)(r0 + ty) * MEM + k0 + 16 + tx] : 0.f;
            bv = ATin[(size_t)(k0 + 16 + ty) * MEM + c0 + tx];
        }
#pragma unroll
        for (int k = 0; k < 16; k++)
            acc = fmaf(Xs[ty][k], Bs[k][tx], acc);
    }
    if (rowOk) Cmat[(size_t)(r0 + ty) * MEM + c0 + tx] = acc;
}

// ---------------- k_G: G=Ht@Wh_m -> transposed fp16 gt ----------------
__global__ __launch_bounds__(256) void k_G(const float* __restrict__ Wh) {
    __shared__ float As[16][32];
    __shared__ float Bs[16][33];
    int r0 = blockIdx.y * 32, c0 = blockIdx.x * 32;   // r=d, c=j
    int tid = threadIdx.x;
    int ar = tid >> 3, ac2 = (tid & 7) * 2;
    int bk = tid >> 4, bj2 = (tid & 15) * 2;
    int ty = tid >> 4, tx = tid & 15;
    float acc[2][2] = {};
    for (int k0 = 0; k0 < MEM; k0 += 16) {
        float2 av = *(const float2*)(g_Ht + (size_t)(r0 + ar) * MEM + k0 + ac2);
        float2 bv = *(const float2*)(Wh + (size_t)(k0 + bk) * HID + c0 + bj2);
        __syncthreads();
        As[ac2][ar] = av.x; As[ac2 + 1][ar] = av.y;
        Bs[bk][bj2] = bv.x; Bs[bk][bj2 + 1] = bv.y;
        __syncthreads();
#pragma unroll
        for (int k = 0; k < 16; k++) {
            float a0 = As[k][ty * 2], a1 = As[k][ty * 2 + 1];
            float b0 = Bs[k][tx * 2], b1 = Bs[k][tx * 2 + 1];
            acc[0][0] = fmaf(a0, b0, acc[0][0]); acc[0][1] = fmaf(a0, b1, acc[0][1]);
            acc[1][0] = fmaf(a1, b0, acc[1][0]); acc[1][1] = fmaf(a1, b1, acc[1][1]);
        }
    }
#pragma unroll
    for (int i = 0; i < 2; i++)
#pragma unroll
        for (int jj = 0; jj < 2; jj++) {
            int d = r0 + ty * 2 + i, j = c0 + tx * 2 + jj;
            g_gt[(size_t)j * SEQ + d] = __float2half(acc[i][jj]);
        }
}

// ---------------- k_main: fp16 2-product fused GEMM, K=64 chunks ----------------
__device__ __forceinline__ void cp_tile64(uint32_t sdst, const __half* __restrict__ g,
                                          int stride, int tid) {
#pragma unroll
    for (int it = 0; it < 4; it++) {
        int q = tid + it * 256;            // [0,1024)
        int row = q >> 3, ch = q & 7;      // 128 rows x 8 x 16B
        cp16(sdst + row * RSB + ch * 16, g + (size_t)row * stride + ch * 8);
    }
}

__global__ __launch_bounds__(256, 2) void k_main(const float* __restrict__ Whb,
                                                 float* __restrict__ out, int write_hn) {
    extern __shared__ __align__(128) char smem[];
    const int b = blockIdx.z;
    const int t0 = blockIdx.y * 128;
    const int j0 = blockIdx.x * 128;
    const int tid = threadIdx.x;
    const int lane = tid & 31;
    const int warp_m = (tid >> 5) & 1;
    const int warp_n = tid >> 6;
    const uint32_t sbase = smem_to_u32(smem);

    {
        const uint32_t* gh = (const uint32_t*)(g_urhi + (size_t)b * URPAD);
        const uint32_t* gl = (const uint32_t*)(g_urlo + (size_t)b * URPAD);
        uint32_t* sh = (uint32_t*)(smem + URS_OFF);
        uint32_t* sl = (uint32_t*)(smem + URS_OFF + 1280);
        for (int q = tid; q < 320; q += 256) { sh[q] = gh[q]; sl[q] = gl[q]; }
    }
    __syncthreads();
    const uint32_t* ursh32 = (const uint32_t*)(smem + URS_OFF);
    const uint32_t* ursl32 = (const uint32_t*)(smem + URS_OFF + 1280);

    const __half* xh = g_xhi + ((size_t)(b * SEQ + t0)) * DIN;
    const __half* xl = g_xlo + ((size_t)(b * SEQ + t0)) * DIN;
    const __half* wt = g_wht + (size_t)j0 * DIN;
    const __half* gt = g_gt + (size_t)j0 * SEQ;

    const int nchunks = 10 + 2 * blockIdx.y;   // 8 dense + (2*by+2) toeplitz

    auto fill = [&](int i, int p) {
        uint32_t sb = sbase + p * BUFB;
        char* sc = smem + p * BUFB;
        if (i < 8) {
            int k0 = i * 64;
            cp_tile64(sb,             xh + k0, DIN, tid);
            cp_tile64(sb + TILEB,     xl + k0, DIN, tid);
            cp_tile64(sb + 2 * TILEB, wt + k0, DIN, tid);
        } else {
            int d0 = (i - 8) * 64;
            cp_tile64(sb + 2 * TILEB, gt + d0, SEQ, tid);
            int r = tid >> 1, hf = tid & 1;
            int s0 = 511 - (t0 + r) + d0 + hf * 32;
            int base = s0 >> 1, par = s0 & 1;
            uint32_t w[16];
            uint32_t w0 = ursh32[base];
#pragma unroll
            for (int c = 0; c < 16; c++) {
                uint32_t w1 = ursh32[base + c + 1];
                w[c] = par ? __byte_perm(w0, w1, 0x5432) : w0;
                w0 = w1;
            }
#pragma unroll
            for (int q = 0; q < 4; q++)
                *(uint4*)(sc + r * RSB + hf * 64 + q * 16) =
                    make_uint4(w[q * 4], w[q * 4 + 1], w[q * 4 + 2], w[q * 4 + 3]);
            w0 = ursl32[base];
#pragma unroll
            for (int c = 0; c < 16; c++) {
                uint32_t w1 = ursl32[base + c + 1];
                w[c] = par ? __byte_perm(w0, w1, 0x5432) : w0;
                w0 = w1;
            }
#pragma unroll
            for (int q = 0; q < 4; q++)
                *(uint4*)(sc + TILEB + r * RSB + hf * 64 + q * 16) =
                    make_uint4(w[q * 4], w[q * 4 + 1], w[q * 4 + 2], w[q * 4 + 3]);
        }
    };

    float acc[4][4][4];
#pragma unroll
    for (int mi = 0; mi < 4; mi++)
#pragma unroll
        for (int ni = 0; ni < 4; ni++)
#pragma unroll
            for (int e = 0; e < 4; e++) acc[mi][ni][e] = 0.f;

    fill(0, 0);
    CP_COMMIT();

    for (int i = 0; i < nchunks; i++) {
        int p = i & 1;
        if (i + 1 < nchunks) { fill(i + 1, p ^ 1); CP_COMMIT(); CP_WAIT1(); }
        else CP_WAIT0();
        __syncthreads();

        uint32_t Abase = sbase + p * BUFB;
        uint32_t Bbase = Abase + 2 * TILEB;
#pragma unroll
        for (int ks = 0; ks < 4; ks++) {
            uint32_t bh[4][2];
#pragma unroll
            for (int np = 0; np < 2; np++) {
                uint32_t r[4];
                uint32_t baddr = Bbase +
                    (warp_n * 32 + np * 16 + (lane & 15)) * RSB +
                    ks * 32 + ((lane >> 4) << 4);
                ldsm4(r, baddr);
                bh[np * 2][0] = r[0];     bh[np * 2][1] = r[2];
                bh[np * 2 + 1][0] = r[1]; bh[np * 2 + 1][1] = r[3];
            }
            uint32_t a[4][4];
            uint32_t aoff = (warp_m * 64 + (lane & 15)) * RSB + ks * 32 + ((lane >> 4) << 4);
#pragma unroll
            for (int mi = 0; mi < 4; mi++) ldsm4(a[mi], Abase + aoff + mi * 16 * RSB);
#pragma unroll
            for (int mi = 0; mi < 4; mi++)
#pragma unroll
                for (int ni = 0; ni < 4; ni++)
                    mma_f16(acc[mi][ni], a[mi], bh[ni]);
#pragma unroll
            for (int mi = 0; mi < 4; mi++) ldsm4(a[mi], Abase + TILEB + aoff + mi * 16 * RSB);
#pragma unroll
            for (int mi = 0; mi < 4; mi++)
#pragma unroll
                for (int ni = 0; ni < 4; ni++)
                    mma_f16(acc[mi][ni], a[mi], bh[ni]);
        }
        __syncthreads();
    }

    // ---- epilogue ----
    const int g4 = lane >> 2, t4 = lane & 3;
    const size_t HN_BASE = (size_t)NBATCH * SEQ * HID;
    float2 bias[4];
#pragma unroll
    for (int ni = 0; ni < 4; ni++)
        bias[ni] = *(const float2*)(Whb + j0 + warp_n * 32 + ni * 8 + t4 * 2);
#pragma unroll
    for (int mi = 0; mi < 4; mi++) {
        int ta = t0 + warp_m * 64 + mi * 16 + g4;
        int tb = ta + 8;
        size_t rowa = ((size_t)b * SEQ + ta) * HID;
        size_t rowb = ((size_t)b * SEQ + tb) * HID;
#pragma unroll
        for (int ni = 0; ni < 4; ni++) {
            int j = j0 + warp_n * 32 + ni * 8 + t4 * 2;
            float2 v0, v1;
            v0.x = fmaxf(acc[mi][ni][0] + bias[ni].x, 0.f);
            v0.y = fmaxf(acc[mi][ni][1] + bias[ni].y, 0.f);
            v1.x = fmaxf(acc[mi][ni][2] + bias[ni].x, 0.f);
            v1.y = fmaxf(acc[mi][ni][3] + bias[ni].y, 0.f);
            *(float2*)(out + rowa + j) = v0;
            *(float2*)(out + rowb + j) = v1;
            if (write_hn && tb == SEQ - 1)
                *(float2*)(out + HN_BASE + (size_t)b * HID + j) = v1;
        }
    }
}

// ---------------- launch ----------------
extern "C" void kernel_launch(void* const* d_in, const int* in_sizes, int n_in,
                              void* d_out, int out_size) {
    const float* x    = (const float*)d_in[0];
    const float* Wu_w = (const float*)d_in[1];
    const float* Wu_b = (const float*)d_in[2];
    const float* Wh_w = (const float*)d_in[3];
    const float* Wh_b = (const float*)d_in[4];
    const float* A    = (const float*)d_in[5];
    const float* B    = (const float*)d_in[6];
    float* out = (float*)d_out;

    int write_hn = (out_size >= NBATCH * SEQ * HID + NBATCH * HID) ? 1 : 0;

    static int smem_set = 0;
    if (!smem_set) {
        cudaFuncSetAttribute(k_main, cudaFuncAttributeMaxDynamicSharedMemorySize, SMEM_DYN);
        smem_set = 1;
    }

    k_ux<<<NBATCH * SEQ / 8, 256>>>(x, Wu_w, Wu_b);
    k_wt<<<dim3(16, 16), 256>>>(Wh_w, A, B);
    int sel = 0;
    for (int n = 1; n <= 256; n <<= 1) {
        int nsq = (n == 256) ? 0 : 256;          // skip final squaring (A^512 unused)
        int exp_blocks = ((n + 15) / 16) * 16;
        k_round2<<<nsq + exp_blocks, 256>>>(sel, n, nsq);
        sel ^= 1;
    }
    k_G<<<dim3(16, 16), 256>>>(Wh_w);
    k_main<<<dim3(HID / 128, SEQ / 128, NBATCH), 256, SMEM_DYN>>>(Wh_b, out, write_hn);
}

// round 8
// speedup vs baseline: 3.1555x; 1.0140x over previous
#include <cuda_runtime.h>
#include <cuda_fp16.h>
#include <cstdint>

#define SEQ 512
#define DIN 512
#define MEM 256
#define HID 512
#define NBATCH 64
#define URPAD 640

#define RSB 144                  // row stride bytes: 64 fp16 = 128 B + 16 pad
#define TILEB (128 * RSB)        // 18432 B
#define BUFB (3 * TILEB)         // A_hi, A_lo, B
#define URS_OFF (2 * BUFB)
#define SMEM_DYN (2 * BUFB + 2 * 1280)

// chain kernel smem: Xs[32][260] floats + Bs[256][32] floats
#define XS_PITCH 260
#define XS_BYTES (32 * XS_PITCH * 4)         // 33280
#define CHAIN_SMEM (XS_BYTES + 256 * 32 * 4) // 33280 + 32768 = 66048
#define CHAIN_GRID 128

// ---------------- static device scratch ----------------
__device__ __align__(16) __half g_xhi[NBATCH * SEQ * DIN];
__device__ __align__(16) __half g_xlo[NBATCH * SEQ * DIN];
__device__ __align__(16) __half g_urhi[NBATCH * URPAD];
__device__ __align__(16) __half g_urlo[NBATCH * URPAD];
__device__ __align__(16) __half g_wht[HID * DIN];    // Wht[j][k] = Wh[256+k][j]
__device__ __align__(16) __half g_gt[HID * SEQ];     // Gt[j][d] = G[d][j]
__device__ float g_Ht[SEQ * MEM];
__device__ float g_AT[2][MEM * MEM];
__device__ unsigned g_count;
__device__ unsigned g_epoch;

// ---------------- helpers ----------------
__device__ __forceinline__ uint32_t smem_to_u32(const void* p) {
    uint32_t a;
    asm("{ .reg .u64 t; cvta.to.shared.u64 t, %1; cvt.u32.u64 %0, t; }" : "=r"(a) : "l"(p));
    return a;
}
__device__ __forceinline__ void cp16(uint32_t dst, const void* src) {
    asm volatile("cp.async.cg.shared.global [%0], [%1], 16;" :: "r"(dst), "l"(src));
}
#define CP_COMMIT() asm volatile("cp.async.commit_group;" ::: "memory")
#define CP_WAIT0()  asm volatile("cp.async.wait_group 0;" ::: "memory")
#define CP_WAIT1()  asm volatile("cp.async.wait_group 1;" ::: "memory")

__device__ __forceinline__ void ldsm4(uint32_t r[4], uint32_t addr) {
    asm volatile("ldmatrix.sync.aligned.m8n8.x4.shared.b16 {%0,%1,%2,%3}, [%4];"
                 : "=r"(r[0]), "=r"(r[1]), "=r"(r[2]), "=r"(r[3]) : "r"(addr));
}
__device__ __forceinline__ void mma_f16(float* c, const uint32_t* a, const uint32_t* b) {
    asm volatile(
        "mma.sync.aligned.m16n8k16.row.col.f32.f16.f16.f32 "
        "{%0,%1,%2,%3}, {%4,%5,%6,%7}, {%8,%9}, {%0,%1,%2,%3};"
        : "+f"(c[0]), "+f"(c[1]), "+f"(c[2]), "+f"(c[3])
        : "r"(a[0]), "r"(a[1]), "r"(a[2]), "r"(a[3]), "r"(b[0]), "r"(b[1]));
}
__device__ __forceinline__ void split2h(float v, __half& h, __half& l) {
    h = __float2half(v);
    l = __float2half(v - __half2float(h));
}

// ---------------- k_ux: u + split x + pad, one pass over x ----------------
__global__ __launch_bounds__(256) void k_ux(const float* __restrict__ x,
                                            const float* __restrict__ wu,
                                            const float* __restrict__ wub) {
    int row = blockIdx.x * 8 + (threadIdx.x >> 5);   // [0, 32768)
    int lane = threadIdx.x & 31;
    const float4* xr = (const float4*)(x + (size_t)row * DIN);
    const float4* wr = (const float4*)wu;
    float s = 0.f;
#pragma unroll
    for (int i = 0; i < 4; i++) {
        float4 v = xr[lane + 32 * i];
        float4 w = wr[lane + 32 * i];
        s += v.x * w.x + v.y * w.y + v.z * w.z + v.w * w.w;
        __half h0, h1, h2, h3, l0, l1, l2, l3;
        split2h(v.x, h0, l0); split2h(v.y, h1, l1); split2h(v.z, h2, l2); split2h(v.w, h3, l3);
        size_t off = (size_t)row * DIN + (lane + 32 * i) * 4;
        __half2 ha = {h0, h1}, hb = {h2, h3}, la = {l0, l1}, lb = {l2, l3};
        *(__half2*)(g_xhi + off) = ha; *(__half2*)(g_xhi + off + 2) = hb;
        *(__half2*)(g_xlo + off) = la; *(__half2*)(g_xlo + off + 2) = lb;
    }
#pragma unroll
    for (int o = 16; o; o >>= 1) s += __shfl_xor_sync(0xffffffffu, s, o);
    if (lane == 0) {
        float u = fmaxf(s + wub[0], 0.f);
        int b = row >> 9, t = row & 511;
        __half h, l; split2h(u, h, l);
        g_urhi[b * URPAD + (511 - t)] = h;
        g_urlo[b * URPAD + (511 - t)] = l;
        if (t < 128) {
            g_urhi[b * URPAD + 512 + t] = __float2half(0.f);
            g_urlo[b * URPAD + 512 + t] = __float2half(0.f);
        }
    }
}

// ---------------- k_wt: transpose Wh_x -> fp16; A^T init; Ht[0]=B; barrier reset ----------------
__global__ __launch_bounds__(256) void k_wt(const float* __restrict__ Wh,
                                            const float* __restrict__ A,
                                            const float* __restrict__ Bv) {
    __shared__ float tile[32][33];
    int kb = blockIdx.x, jb = blockIdx.y;
    int bid = jb * 16 + kb;                       // [0,256)
    g_AT[0][bid * MEM + threadIdx.x] = A[(size_t)threadIdx.x * MEM + bid];
    if (bid == 0) g_Ht[threadIdx.x] = Bv[threadIdx.x];
    if (bid == 0 && threadIdx.x == 0) { g_count = 0; g_epoch = 0; }

    int tx = threadIdx.x & 31, ty = threadIdx.x >> 5;
    for (int yy = ty; yy < 32; yy += 8)
        tile[yy][tx] = Wh[(size_t)(MEM + kb * 32 + yy) * HID + jb * 32 + tx];
    __syncthreads();
    for (int yy = ty; yy < 32; yy += 8) {
        float v = tile[tx][yy];
        int j = jb * 32 + yy, k = kb * 32 + tx;
        g_wht[(size_t)j * DIN + k] = __float2half(v);
    }
}

// ---------------- k_chain: all 9 doubling rounds + G, one persistent kernel ----------------
__device__ __forceinline__ void grid_barrier(int bar) {
    __threadfence();
    __syncthreads();
    if (threadIdx.x == 0) {
        unsigned my = atomicAdd(&g_count, 1u);
        if (my == (unsigned)(CHAIN_GRID * bar - 1)) {
            atomicAdd(&g_epoch, 1u);
        } else {
            while (atomicAdd(&g_epoch, 0u) < (unsigned)bar) { }
        }
    }
    __syncthreads();
}

__global__ __launch_bounds__(256) void k_chain(const float* __restrict__ Wh) {
    extern __shared__ __align__(16) float csmem[];
    float* Xs = csmem;                         // [32][XS_PITCH]
    float* Bs = csmem + 32 * XS_PITCH;         // [256][32]
    const int bid = blockIdx.x, tid = threadIdx.x;
    const int ty = tid >> 4, tx = tid & 15;    // 2x2 micro-tile

    for (int r = 0; r <= 8; r++) {
        int n = 1 << r;
        int sel = r & 1;
        int nsq = (r < 8) ? 64 : 0;            // skip final squaring (A^512 unused)
        int nrt = (n + 31) / 32;
        int ntiles = nsq + nrt * 8;
        const float* __restrict__ ATin = g_AT[sel];
        for (int t = bid; t < ntiles; t += CHAIN_GRID) {
            const float* Amat; float* Cmat; int rows, tr, tc;
            if (t < nsq) { Amat = ATin; Cmat = g_AT[sel ^ 1]; rows = MEM; tr = t >> 3; tc = t & 7; }
            else { int te = t - nsq; Amat = g_Ht; Cmat = g_Ht + (size_t)n * MEM; rows = n; tr = te >> 3; tc = te & 7; }
            int r0 = tr * 32, c0 = tc * 32;
            __syncthreads();
            for (int q = tid; q < 2048; q += 256) {
                int row = q >> 6, c4 = (q & 63) * 4;
                float4 v = make_float4(0.f, 0.f, 0.f, 0.f);
                if (r0 + row < rows) v = *(const float4*)(Amat + (size_t)(r0 + row) * MEM + c4);
                *(float4*)&Xs[row * XS_PITCH + c4] = v;
                int brow = q >> 3, bc4 = (q & 7) * 4;
                *(float4*)&Bs[brow * 32 + bc4] = *(const float4*)(ATin + (size_t)brow * MEM + c0 + bc4);
            }
            __syncthreads();
            float acc[2][2] = {};
#pragma unroll 8
            for (int k = 0; k < MEM; k++) {
                float a0 = Xs[(ty * 2) * XS_PITCH + k], a1 = Xs[(ty * 2 + 1) * XS_PITCH + k];
                float b0 = Bs[k * 32 + tx * 2],         b1 = Bs[k * 32 + tx * 2 + 1];
                acc[0][0] = fmaf(a0, b0, acc[0][0]); acc[0][1] = fmaf(a0, b1, acc[0][1]);
                acc[1][0] = fmaf(a1, b0, acc[1][0]); acc[1][1] = fmaf(a1, b1, acc[1][1]);
            }
#pragma unroll
            for (int i = 0; i < 2; i++) {
                int rr = r0 + ty * 2 + i;
                if (rr < rows) {
                    Cmat[(size_t)rr * MEM + c0 + tx * 2]     = acc[i][0];
                    Cmat[(size_t)rr * MEM + c0 + tx * 2 + 1] = acc[i][1];
                }
            }
        }
        grid_barrier(r + 1);
    }

    // ---- G phase: G = Ht @ Wh_m -> gt[j][d] fp16 (same sequential-k order as before) ----
    for (int t = bid; t < 256; t += CHAIN_GRID) {
        int tr = t >> 4, tc = t & 15;
        int d0 = tr * 32, j0 = tc * 32;
        __syncthreads();
        for (int q = tid; q < 2048; q += 256) {
            int row = q >> 6, c4 = (q & 63) * 4;
            *(float4*)&Xs[row * XS_PITCH + c4] = *(const float4*)(g_Ht + (size_t)(d0 + row) * MEM + c4);
            int brow = q >> 3, bc4 = (q & 7) * 4;
            *(float4*)&Bs[brow * 32 + bc4] = *(const float4*)(Wh + (size_t)brow * HID + j0 + bc4);
        }
        __syncthreads();
        float acc[2][2] = {};
#pragma unroll 8
        for (int k = 0; k < MEM; k++) {
            float a0 = Xs[(ty * 2) * XS_PITCH + k], a1 = Xs[(ty * 2 + 1) * XS_PITCH + k];
            float b0 = Bs[k * 32 + tx * 2],         b1 = Bs[k * 32 + tx * 2 + 1];
            acc[0][0] = fmaf(a0, b0, acc[0][0]); acc[0][1] = fmaf(a0, b1, acc[0][1]);
            acc[1][0] = fmaf(a1, b0, acc[1][0]); acc[1][1] = fmaf(a1, b1, acc[1][1]);
        }
#pragma unroll
        for (int i = 0; i < 2; i++)
#pragma unroll
            for (int jj = 0; jj < 2; jj++) {
                int d = d0 + ty * 2 + i, j = j0 + tx * 2 + jj;
                g_gt[(size_t)j * SEQ + d] = __float2half(acc[i][jj]);
            }
    }
}

// ---------------- k_main: fp16 2-product fused GEMM, K=64 chunks ----------------
__device__ __forceinline__ void cp_tile64(uint32_t sdst, const __half* __restrict__ g,
                                          int stride, int tid) {
#pragma unroll
    for (int it = 0; it < 4; it++) {
        int q = tid + it * 256;            // [0,1024)
        int row = q >> 3, ch = q & 7;      // 128 rows x 8 x 16B
        cp16(sdst + row * RSB + ch * 16, g + (size_t)row * stride + ch * 8);
    }
}

__global__ __launch_bounds__(256, 2) void k_main(const float* __restrict__ Whb,
                                                 float* __restrict__ out, int write_hn) {
    extern __shared__ __align__(128) char smem[];
    const int b = blockIdx.z;
    const int t0 = blockIdx.y * 128;
    const int j0 = blockIdx.x * 128;
    const int tid = threadIdx.x;
    const int lane = tid & 31;
    const int warp_m = (tid >> 5) & 1;
    const int warp_n = tid >> 6;
    const uint32_t sbase = smem_to_u32(smem);

    {
        const uint32_t* gh = (const uint32_t*)(g_urhi + (size_t)b * URPAD);
        const uint32_t* gl = (const uint32_t*)(g_urlo + (size_t)b * URPAD);
        uint32_t* sh = (uint32_t*)(smem + URS_OFF);
        uint32_t* sl = (uint32_t*)(smem + URS_OFF + 1280);
        for (int q = tid; q < 320; q += 256) { sh[q] = gh[q]; sl[q] = gl[q]; }
    }
    __syncthreads();
    const uint32_t* ursh32 = (const uint32_t*)(smem + URS_OFF);
    const uint32_t* ursl32 = (const uint32_t*)(smem + URS_OFF + 1280);

    const __half* xh = g_xhi + ((size_t)(b * SEQ + t0)) * DIN;
    const __half* xl = g_xlo + ((size_t)(b * SEQ + t0)) * DIN;
    const __half* wt = g_wht + (size_t)j0 * DIN;
    const __half* gt = g_gt + (size_t)j0 * SEQ;

    const int nchunks = 10 + 2 * blockIdx.y;

    auto fill = [&](int i, int p) {
        uint32_t sb = sbase + p * BUFB;
        char* sc = smem + p * BUFB;
        if (i < 8) {
            int k0 = i * 64;
            cp_tile64(sb,             xh + k0, DIN, tid);
            cp_tile64(sb + TILEB,     xl + k0, DIN, tid);
            cp_tile64(sb + 2 * TILEB, wt + k0, DIN, tid);
        } else {
            int d0 = (i - 8) * 64;
            cp_tile64(sb + 2 * TILEB, gt + d0, SEQ, tid);
            int r = tid >> 1, hf = tid & 1;
            int s0 = 511 - (t0 + r) + d0 + hf * 32;
            int base = s0 >> 1, par = s0 & 1;
            uint32_t w[16];
            uint32_t w0 = ursh32[base];
#pragma unroll
            for (int c = 0; c < 16; c++) {
                uint32_t w1 = ursh32[base + c + 1];
                w[c] = par ? __byte_perm(w0, w1, 0x5432) : w0;
                w0 = w1;
            }
#pragma unroll
            for (int q = 0; q < 4; q++)
                *(uint4*)(sc + r * RSB + hf * 64 + q * 16) =
                    make_uint4(w[q * 4], w[q * 4 + 1], w[q * 4 + 2], w[q * 4 + 3]);
            w0 = ursl32[base];
#pragma unroll
            for (int c = 0; c < 16; c++) {
                uint32_t w1 = ursl32[base + c + 1];
                w[c] = par ? __byte_perm(w0, w1, 0x5432) : w0;
                w0 = w1;
            }
#pragma unroll
            for (int q = 0; q < 4; q++)
                *(uint4*)(sc + TILEB + r * RSB + hf * 64 + q * 16) =
                    make_uint4(w[q * 4], w[q * 4 + 1], w[q * 4 + 2], w[q * 4 + 3]);
        }
    };

    float acc[4][4][4];
#pragma unroll
    for (int mi = 0; mi < 4; mi++)
#pragma unroll
        for (int ni = 0; ni < 4; ni++)
#pragma unroll
            for (int e = 0; e < 4; e++) acc[mi][ni][e] = 0.f;

    fill(0, 0);
    CP_COMMIT();

    for (int i = 0; i < nchunks; i++) {
        int p = i & 1;
        if (i + 1 < nchunks) { fill(i + 1, p ^ 1); CP_COMMIT(); CP_WAIT1(); }
        else CP_WAIT0();
        __syncthreads();

        uint32_t Abase = sbase + p * BUFB;
        uint32_t Bbase = Abase + 2 * TILEB;
#pragma unroll
        for (int ks = 0; ks < 4; ks++) {
            uint32_t bh[4][2];
#pragma unroll
            for (int np = 0; np < 2; np++) {
                uint32_t r[4];
                uint32_t baddr = Bbase +
                    (warp_n * 32 + np * 16 + (lane & 15)) * RSB +
                    ks * 32 + ((lane >> 4) << 4);
                ldsm4(r, baddr);
                bh[np * 2][0] = r[0];     bh[np * 2][1] = r[2];
                bh[np * 2 + 1][0] = r[1]; bh[np * 2 + 1][1] = r[3];
            }
            uint32_t a[4][4];
            uint32_t aoff = (warp_m * 64 + (lane & 15)) * RSB + ks * 32 + ((lane >> 4) << 4);
#pragma unroll
            for (int mi = 0; mi < 4; mi++) ldsm4(a[mi], Abase + aoff + mi * 16 * RSB);
#pragma unroll
            for (int mi = 0; mi < 4; mi++)
#pragma unroll
                for (int ni = 0; ni < 4; ni++)
                    mma_f16(acc[mi][ni], a[mi], bh[ni]);
#pragma unroll
            for (int mi = 0; mi < 4; mi++) ldsm4(a[mi], Abase + TILEB + aoff + mi * 16 * RSB);
#pragma unroll
            for (int mi = 0; mi < 4; mi++)
#pragma unroll
                for (int ni = 0; ni < 4; ni++)
                    mma_f16(acc[mi][ni], a[mi], bh[ni]);
        }
        __syncthreads();
    }

    // ---- epilogue ----
    const int g4 = lane >> 2, t4 = lane & 3;
    const size_t HN_BASE = (size_t)NBATCH * SEQ * HID;
    float2 bias[4];
#pragma unroll
    for (int ni = 0; ni < 4; ni++)
        bias[ni] = *(const float2*)(Whb + j0 + warp_n * 32 + ni * 8 + t4 * 2);
#pragma unroll
    for (int mi = 0; mi < 4; mi++) {
        int ta = t0 + warp_m * 64 + mi * 16 + g4;
        int tb = ta + 8;
        size_t rowa = ((size_t)b * SEQ + ta) * HID;
        size_t rowb = ((size_t)b * SEQ + tb) * HID;
#pragma unroll
        for (int ni = 0; ni < 4; ni++) {
            int j = j0 + warp_n * 32 + ni * 8 + t4 * 2;
            float2 v0, v1;
            v0.x = fmaxf(acc[mi][ni][0] + bias[ni].x, 0.f);
            v0.y = fmaxf(acc[mi][ni][1] + bias[ni].y, 0.f);
            v1.x = fmaxf(acc[mi][ni][2] + bias[ni].x, 0.f);
            v1.y = fmaxf(acc[mi][ni][3] + bias[ni].y, 0.f);
            *(float2*)(out + rowa + j) = v0;
            *(float2*)(out + rowb + j) = v1;
            if (write_hn && tb == SEQ - 1)
                *(float2*)(out + HN_BASE + (size_t)b * HID + j) = v1;
        }
    }
}

// ---------------- launch ----------------
extern "C" void kernel_launch(void* const* d_in, const int* in_sizes, int n_in,
                              void* d_out, int out_size) {
    const float* x    = (const float*)d_in[0];
    const float* Wu_w = (const float*)d_in[1];
    const float* Wu_b = (const float*)d_in[2];
    const float* Wh_w = (const float*)d_in[3];
    const float* Wh_b = (const float*)d_in[4];
    const float* A    = (const float*)d_in[5];
    const float* B    = (const float*)d_in[6];
    float* out = (float*)d_out;

    int write_hn = (out_size >= NBATCH * SEQ * HID + NBATCH * HID) ? 1 : 0;

    static int smem_set = 0;
    if (!smem_set) {
        cudaFuncSetAttribute(k_main, cudaFuncAttributeMaxDynamicSharedMemorySize, SMEM_DYN);
        cudaFuncSetAttribute(k_chain, cudaFuncAttributeMaxDynamicSharedMemorySize, CHAIN_SMEM);
        smem_set = 1;
    }

    k_ux<<<NBATCH * SEQ / 8, 256>>>(x, Wu_w, Wu_b);
    k_wt<<<dim3(16, 16), 256>>>(Wh_w, A, B);          // also resets barrier state
    k_chain<<<CHAIN_GRID, 256, CHAIN_SMEM>>>(Wh_w);   // 9 rounds + G, one launch
    k_main<<<dim3(HID / 128, SEQ / 128, NBATCH), 256, SMEM_DYN>>>(Wh_b, out, write_hn);
}

// round 9
// speedup vs baseline: 4.4619x; 1.4140x over previous
#include <cuda_runtime.h>
#include <cuda_fp16.h>
#include <cstdint>

#define SEQ 512
#define DIN 512
#define MEM 256
#define HID 512
#define NBATCH 64
#define URPAD 640

#define RSB 144                  // row stride bytes: 64 fp16 = 128 B + 16 pad
#define TILEB (128 * RSB)        // 18432 B
#define BUFB (2 * TILEB)         // A, B tiles
#define URS_OFF (2 * BUFB)
#define SMEM_DYN (2 * BUFB + 1280)

// chain kernel smem: Xs[32][260] floats + Bs[256][32] floats
#define XS_PITCH 260
#define XS_BYTES (32 * XS_PITCH * 4)
#define CHAIN_SMEM (XS_BYTES + 256 * 32 * 4)
#define CHAIN_GRID 128

// ---------------- static device scratch ----------------
__device__ __align__(16) __half g_xh[NBATCH * SEQ * DIN];
__device__ __align__(16) __half g_urh[NBATCH * URPAD];
__device__ __align__(16) __half g_wht[HID * DIN];    // Wht[j][k] = Wh[256+k][j]
__device__ __align__(16) __half g_gt[HID * SEQ];     // Gt[j][d] = G[d][j]
__device__ float g_Ht[SEQ * MEM];
__device__ float g_AT[2][MEM * MEM];
__device__ unsigned g_count;
__device__ unsigned g_epoch;

// ---------------- helpers ----------------
__device__ __forceinline__ uint32_t smem_to_u32(const void* p) {
    uint32_t a;
    asm("{ .reg .u64 t; cvta.to.shared.u64 t, %1; cvt.u32.u64 %0, t; }" : "=r"(a) : "l"(p));
    return a;
}
__device__ __forceinline__ void cp16(uint32_t dst, const void* src) {
    asm volatile("cp.async.cg.shared.global [%0], [%1], 16;" :: "r"(dst), "l"(src));
}
#define CP_COMMIT() asm volatile("cp.async.commit_group;" ::: "memory")
#define CP_WAIT0()  asm volatile("cp.async.wait_group 0;" ::: "memory")
#define CP_WAIT1()  asm volatile("cp.async.wait_group 1;" ::: "memory")

__device__ __forceinline__ void ldsm4(uint32_t r[4], uint32_t addr) {
    asm volatile("ldmatrix.sync.aligned.m8n8.x4.shared.b16 {%0,%1,%2,%3}, [%4];"
                 : "=r"(r[0]), "=r"(r[1]), "=r"(r[2]), "=r"(r[3]) : "r"(addr));
}
__device__ __forceinline__ void mma_f16(float* c, const uint32_t* a, const uint32_t* b) {
    asm volatile(
        "mma.sync.aligned.m16n8k16.row.col.f32.f16.f16.f32 "
        "{%0,%1,%2,%3}, {%4,%5,%6,%7}, {%8,%9}, {%0,%1,%2,%3};"
        : "+f"(c[0]), "+f"(c[1]), "+f"(c[2]), "+f"(c[3])
        : "r"(a[0]), "r"(a[1]), "r"(a[2]), "r"(a[3]), "r"(b[0]), "r"(b[1]));
}

// ---------------- k_ux: u = relu(x@Wu+b) + fp16 x, one pass ----------------
__global__ __launch_bounds__(256) void k_ux(const float* __restrict__ x,
                                            const float* __restrict__ wu,
                                            const float* __restrict__ wub) {
    int row = blockIdx.x * 8 + (threadIdx.x >> 5);   // [0, 32768)
    int lane = threadIdx.x & 31;
    const float4* xr = (const float4*)(x + (size_t)row * DIN);
    const float4* wr = (const float4*)wu;
    float s = 0.f;
#pragma unroll
    for (int i = 0; i < 4; i++) {
        float4 v = xr[lane + 32 * i];
        float4 w = wr[lane + 32 * i];
        s += v.x * w.x + v.y * w.y + v.z * w.z + v.w * w.w;
        size_t off = (size_t)row * DIN + (lane + 32 * i) * 4;
        __half2 ha = {__float2half(v.x), __float2half(v.y)};
        __half2 hb = {__float2half(v.z), __float2half(v.w)};
        *(__half2*)(g_xh + off) = ha; *(__half2*)(g_xh + off + 2) = hb;
    }
#pragma unroll
    for (int o = 16; o; o >>= 1) s += __shfl_xor_sync(0xffffffffu, s, o);
    if (lane == 0) {
        float u = fmaxf(s + wub[0], 0.f);
        int b = row >> 9, t = row & 511;
        g_urh[b * URPAD + (511 - t)] = __float2half(u);
        if (t < 128) g_urh[b * URPAD + 512 + t] = __float2half(0.f);
    }
}

// ---------------- k_wt: transpose Wh_x -> fp16; A^T init; Ht[0]=B; barrier reset ----------------
__global__ __launch_bounds__(256) void k_wt(const float* __restrict__ Wh,
                                            const float* __restrict__ A,
                                            const float* __restrict__ Bv) {
    __shared__ float tile[32][33];
    int kb = blockIdx.x, jb = blockIdx.y;
    int bid = jb * 16 + kb;                       // [0,256)
    g_AT[0][bid * MEM + threadIdx.x] = A[(size_t)threadIdx.x * MEM + bid];
    if (bid == 0) g_Ht[threadIdx.x] = Bv[threadIdx.x];
    if (bid == 0 && threadIdx.x == 0) { g_count = 0; g_epoch = 0; }

    int tx = threadIdx.x & 31, ty = threadIdx.x >> 5;
    for (int yy = ty; yy < 32; yy += 8)
        tile[yy][tx] = Wh[(size_t)(MEM + kb * 32 + yy) * HID + jb * 32 + tx];
    __syncthreads();
    for (int yy = ty; yy < 32; yy += 8) {
        float v = tile[tx][yy];
        int j = jb * 32 + yy, k = kb * 32 + tx;
        g_wht[(size_t)j * DIN + k] = __float2half(v);
    }
}

// ---------------- k_chain: 9 doubling rounds + G, persistent ----------------
__device__ __forceinline__ void grid_barrier(int bar) {
    __threadfence();
    __syncthreads();
    if (threadIdx.x == 0) {
        unsigned my = atomicAdd(&g_count, 1u);
        if (my == (unsigned)(CHAIN_GRID * bar - 1)) {
            atomicAdd(&g_epoch, 1u);
        } else {
            while (atomicAdd(&g_epoch, 0u) < (unsigned)bar) { }
        }
    }
    __syncthreads();
}

__global__ __launch_bounds__(256) void k_chain(const float* __restrict__ Wh) {
    extern __shared__ __align__(16) float csmem[];
    float* Xs = csmem;
    float* Bs = csmem + 32 * XS_PITCH;
    const int bid = blockIdx.x, tid = threadIdx.x;
    const int ty = tid >> 4, tx = tid & 15;

    for (int r = 0; r <= 8; r++) {
        int n = 1 << r;
        int sel = r & 1;
        int nsq = (r < 8) ? 64 : 0;
        int nrt = (n + 31) / 32;
        int ntiles = nsq + nrt * 8;
        const float* __restrict__ ATin = g_AT[sel];
        for (int t = bid; t < ntiles; t += CHAIN_GRID) {
            const float* Amat; float* Cmat; int rows, tr, tc;
            if (t < nsq) { Amat = ATin; Cmat = g_AT[sel ^ 1]; rows = MEM; tr = t >> 3; tc = t & 7; }
            else { int te = t - nsq; Amat = g_Ht; Cmat = g_Ht + (size_t)n * MEM; rows = n; tr = te >> 3; tc = te & 7; }
            int r0 = tr * 32, c0 = tc * 32;
            __syncthreads();
            for (int q = tid; q < 2048; q += 256) {
                int row = q >> 6, c4 = (q & 63) * 4;
                float4 v = make_float4(0.f, 0.f, 0.f, 0.f);
                if (r0 + row < rows) v = *(const float4*)(Amat + (size_t)(r0 + row) * MEM + c4);
                *(float4*)&Xs[row * XS_PITCH + c4] = v;
                int brow = q >> 3, bc4 = (q & 7) * 4;
                *(float4*)&Bs[brow * 32 + bc4] = *(const float4*)(ATin + (size_t)brow * MEM + c0 + bc4);
            }
            __syncthreads();
            float acc[2][2] = {};
#pragma unroll 8
            for (int k = 0; k < MEM; k++) {
                float a0 = Xs[(ty * 2) * XS_PITCH + k], a1 = Xs[(ty * 2 + 1) * XS_PITCH + k];
                float b0 = Bs[k * 32 + tx * 2],         b1 = Bs[k * 32 + tx * 2 + 1];
                acc[0][0] = fmaf(a0, b0, acc[0][0]); acc[0][1] = fmaf(a0, b1, acc[0][1]);
                acc[1][0] = fmaf(a1, b0, acc[1][0]); acc[1][1] = fmaf(a1, b1, acc[1][1]);
            }
#pragma unroll
            for (int i = 0; i < 2; i++) {
                int rr = r0 + ty * 2 + i;
                if (rr < rows) {
                    Cmat[(size_t)rr * MEM + c0 + tx * 2]     = acc[i][0];
                    Cmat[(size_t)rr * MEM + c0 + tx * 2 + 1] = acc[i][1];
                }
            }
        }
        grid_barrier(r + 1);
    }

    for (int t = bid; t < 256; t += CHAIN_GRID) {
        int tr = t >> 4, tc = t & 15;
        int d0 = tr * 32, j0 = tc * 32;
        __syncthreads();
        for (int q = tid; q < 2048; q += 256) {
            int row = q >> 6, c4 = (q & 63) * 4;
            *(float4*)&Xs[row * XS_PITCH + c4] = *(const float4*)(g_Ht + (size_t)(d0 + row) * MEM + c4);
            int brow = q >> 3, bc4 = (q & 7) * 4;
            *(float4*)&Bs[brow * 32 + bc4] = *(const float4*)(Wh + (size_t)brow * HID + j0 + bc4);
        }
        __syncthreads();
        float acc[2][2] = {};
#pragma unroll 8
        for (int k = 0; k < MEM; k++) {
            float a0 = Xs[(ty * 2) * XS_PITCH + k], a1 = Xs[(ty * 2 + 1) * XS_PITCH + k];
            float b0 = Bs[k * 32 + tx * 2],         b1 = Bs[k * 32 + tx * 2 + 1];
            acc[0][0] = fmaf(a0, b0, acc[0][0]); acc[0][1] = fmaf(a0, b1, acc[0][1]);
            acc[1][0] = fmaf(a1, b0, acc[1][0]); acc[1][1] = fmaf(a1, b1, acc[1][1]);
        }
#pragma unroll
        for (int i = 0; i < 2; i++)
#pragma unroll
            for (int jj = 0; jj < 2; jj++) {
                int d = d0 + ty * 2 + i, j = j0 + tx * 2 + jj;
                g_gt[(size_t)j * SEQ + d] = __float2half(acc[i][jj]);
            }
    }
}

// ---------------- k_main: single-product fp16 fused GEMM, K=64 chunks ----------------
__device__ __forceinline__ void cp_tile64(uint32_t sdst, const __half* __restrict__ g,
                                          int stride, int tid) {
#pragma unroll
    for (int it = 0; it < 4; it++) {
        int q = tid + it * 256;
        int row = q >> 3, ch = q & 7;
        cp16(sdst + row * RSB + ch * 16, g + (size_t)row * stride + ch * 8);
    }
}

__global__ __launch_bounds__(256, 2) void k_main(const float* __restrict__ Whb,
                                                 float* __restrict__ out, int write_hn) {
    extern __shared__ __align__(128) char smem[];
    const int b = blockIdx.z;
    const int t0 = blockIdx.y * 128;
    const int j0 = blockIdx.x * 128;
    const int tid = threadIdx.x;
    const int lane = tid & 31;
    const int warp_m = (tid >> 5) & 1;
    const int warp_n = tid >> 6;
    const uint32_t sbase = smem_to_u32(smem);

    {
        const uint32_t* gh = (const uint32_t*)(g_urh + (size_t)b * URPAD);
        uint32_t* sh = (uint32_t*)(smem + URS_OFF);
        for (int q = tid; q < 320; q += 256) sh[q] = gh[q];
    }
    __syncthreads();
    const uint32_t* ursh32 = (const uint32_t*)(smem + URS_OFF);

    const __half* xh = g_xh + ((size_t)(b * SEQ + t0)) * DIN;
    const __half* wt = g_wht + (size_t)j0 * DIN;
    const __half* gt = g_gt + (size_t)j0 * SEQ;

    const int nchunks = 10 + 2 * blockIdx.y;

    auto fill = [&](int i, int p) {
        uint32_t sb = sbase + p * BUFB;
        char* sc = smem + p * BUFB;
        if (i < 8) {
            int k0 = i * 64;
            cp_tile64(sb,         xh + k0, DIN, tid);
            cp_tile64(sb + TILEB, wt + k0, DIN, tid);
        } else {
            int d0 = (i - 8) * 64;
            cp_tile64(sb + TILEB, gt + d0, SEQ, tid);
            int r = tid >> 1, hf = tid & 1;
            int s0 = 511 - (t0 + r) + d0 + hf * 32;
            int base = s0 >> 1, par = s0 & 1;
            uint32_t w[16];
            uint32_t w0 = ursh32[base];
#pragma unroll
            for (int c = 0; c < 16; c++) {
                uint32_t w1 = ursh32[base + c + 1];
                w[c] = par ? __byte_perm(w0, w1, 0x5432) : w0;
                w0 = w1;
            }
#pragma unroll
            for (int q = 0; q < 4; q++)
                *(uint4*)(sc + r * RSB + hf * 64 + q * 16) =
                    make_uint4(w[q * 4], w[q * 4 + 1], w[q * 4 + 2], w[q * 4 + 3]);
        }
    };

    float acc[4][4][4];
#pragma unroll
    for (int mi = 0; mi < 4; mi++)
#pragma unroll
        for (int ni = 0; ni < 4; ni++)
#pragma unroll
            for (int e = 0; e < 4; e++) acc[mi][ni][e] = 0.f;

    fill(0, 0);
    CP_COMMIT();

    // hoisted fragment address bases
    const uint32_t a_base_off = (warp_m * 64 + (lane & 15)) * RSB + ((lane >> 4) << 4);
    const uint32_t b_base_off = TILEB + (warp_n * 32 + (lane & 15)) * RSB + ((lane >> 4) << 4);

    for (int i = 0; i < nchunks; i++) {
        int p = i & 1;
        if (i + 1 < nchunks) { fill(i + 1, p ^ 1); CP_COMMIT(); CP_WAIT1(); }
        else CP_WAIT0();
        __syncthreads();

        uint32_t base = sbase + p * BUFB;
#pragma unroll
        for (int ks = 0; ks < 4; ks++) {
            uint32_t bh[4][2];
            {
                uint32_t r[4];
                uint32_t baddr = base + b_base_off + ks * 32;
                ldsm4(r, baddr);
                bh[0][0] = r[0]; bh[0][1] = r[2];
                bh[1][0] = r[1]; bh[1][1] = r[3];
                ldsm4(r, baddr + 16 * RSB);
                bh[2][0] = r[0]; bh[2][1] = r[2];
                bh[3][0] = r[1]; bh[3][1] = r[3];
            }
            uint32_t a[4][4];
            uint32_t aaddr = base + a_base_off + ks * 32;
#pragma unroll
            for (int mi = 0; mi < 4; mi++) ldsm4(a[mi], aaddr + mi * 16 * RSB);
#pragma unroll
            for (int mi = 0; mi < 4; mi++)
#pragma unroll
                for (int ni = 0; ni < 4; ni++)
                    mma_f16(acc[mi][ni], a[mi], bh[ni]);
        }
        __syncthreads();
    }

    // ---- epilogue ----
    const int g4 = lane >> 2, t4 = lane & 3;
    const size_t HN_BASE = (size_t)NBATCH * SEQ * HID;
    float2 bias[4];
#pragma unroll
    for (int ni = 0; ni < 4; ni++)
        bias[ni] = *(const float2*)(Whb + j0 + warp_n * 32 + ni * 8 + t4 * 2);
#pragma unroll
    for (int mi = 0; mi < 4; mi++) {
        int ta = t0 + warp_m * 64 + mi * 16 + g4;
        int tb = ta + 8;
        size_t rowa = ((size_t)b * SEQ + ta) * HID;
        size_t rowb = ((size_t)b * SEQ + tb) * HID;
#pragma unroll
        for (int ni = 0; ni < 4; ni++) {
            int j = j0 + warp_n * 32 + ni * 8 + t4 * 2;
            float2 v0, v1;
            v0.x = fmaxf(acc[mi][ni][0] + bias[ni].x, 0.f);
            v0.y = fmaxf(acc[mi][ni][1] + bias[ni].y, 0.f);
            v1.x = fmaxf(acc[mi][ni][2] + bias[ni].x, 0.f);
            v1.y = fmaxf(acc[mi][ni][3] + bias[ni].y, 0.f);
            *(float2*)(out + rowa + j) = v0;
            *(float2*)(out + rowb + j) = v1;
            if (write_hn && tb == SEQ - 1)
                *(float2*)(out + HN_BASE + (size_t)b * HID + j) = v1;
        }
    }
}

// ---------------- launch ----------------
extern "C" void kernel_launch(void* const* d_in, const int* in_sizes, int n_in,
                              void* d_out, int out_size) {
    const float* x    = (const float*)d_in[0];
    const float* Wu_w = (const float*)d_in[1];
    const float* Wu_b = (const float*)d_in[2];
    const float* Wh_w = (const float*)d_in[3];
    const float* Wh_b = (const float*)d_in[4];
    const float* A    = (const float*)d_in[5];
    const float* B    = (const float*)d_in[6];
    float* out = (float*)d_out;

    int write_hn = (out_size >= NBATCH * SEQ * HID + NBATCH * HID) ? 1 : 0;

    static int smem_set = 0;
    if (!smem_set) {
        cudaFuncSetAttribute(k_main, cudaFuncAttributeMaxDynamicSharedMemorySize, SMEM_DYN);
        cudaFuncSetAttribute(k_chain, cudaFuncAttributeMaxDynamicSharedMemorySize, CHAIN_SMEM);
        smem_set = 1;
    }

    k_ux<<<NBATCH * SEQ / 8, 256>>>(x, Wu_w, Wu_b);
    k_wt<<<dim3(16, 16), 256>>>(Wh_w, A, B);
    k_chain<<<CHAIN_GRID, 256, CHAIN_SMEM>>>(Wh_w);
    k_main<<<dim3(HID / 128, SEQ / 128, NBATCH), 256, SMEM_DYN>>>(Wh_b, out, write_hn);
}

// round 10
// speedup vs baseline: 4.5051x; 1.0097x over previous
#include <cuda_runtime.h>
#include <cuda_fp16.h>
#include <cstdint>

#define SEQ 512
#define DIN 512
#define MEM 256
#define HID 512
#define NBATCH 64
#define URPAD 640

#define RSB 144                  // row stride bytes: 64 fp16 = 128 B + 16 pad
#define TILEB (128 * RSB)        // 18432 B
#define BUFB (2 * TILEB)         // A, B tiles
#define URS_OFF (2 * BUFB)
#define SMEM_DYN (2 * BUFB + 1280)

// chain smem: Xs[32][260] floats + Bs[256][32] floats
#define XS_PITCH 260
#define XS_BYTES (32 * XS_PITCH * 4)
#define CHAIN_SMEM (XS_BYTES + 256 * 32 * 4)   // 66048
#define PRE_CHAIN 128
#define UX_BLOCKS 4096
#define WT_BLOCKS 256
#define PRE_GRID (PRE_CHAIN + UX_BLOCKS + WT_BLOCKS)

// ---------------- static device scratch ----------------
__device__ __align__(16) __half g_xh[NBATCH * SEQ * DIN];
__device__ __align__(16) __half g_urh[NBATCH * URPAD];
__device__ __align__(16) __half g_wht[HID * DIN];    // Wht[j][k] = Wh[256+k][j]
__device__ __align__(16) __half g_gt[HID * SEQ];     // Gt[j][d] = G[d][j]
__device__ float g_Ht[SEQ * MEM];
__device__ float g_AT[2][MEM * MEM];
__device__ unsigned g_count;   // zero at load; reset by k_main tail each run
__device__ unsigned g_epoch;

// ---------------- helpers ----------------
__device__ __forceinline__ uint32_t smem_to_u32(const void* p) {
    uint32_t a;
    asm("{ .reg .u64 t; cvta.to.shared.u64 t, %1; cvt.u32.u64 %0, t; }" : "=r"(a) : "l"(p));
    return a;
}
__device__ __forceinline__ void cp16(uint32_t dst, const void* src) {
    asm volatile("cp.async.cg.shared.global [%0], [%1], 16;" :: "r"(dst), "l"(src));
}
#define CP_COMMIT() asm volatile("cp.async.commit_group;" ::: "memory")
#define CP_WAIT0()  asm volatile("cp.async.wait_group 0;" ::: "memory")
#define CP_WAIT1()  asm volatile("cp.async.wait_group 1;" ::: "memory")

__device__ __forceinline__ void ldsm4(uint32_t r[4], uint32_t addr) {
    asm volatile("ldmatrix.sync.aligned.m8n8.x4.shared.b16 {%0,%1,%2,%3}, [%4];"
                 : "=r"(r[0]), "=r"(r[1]), "=r"(r[2]), "=r"(r[3]) : "r"(addr));
}
__device__ __forceinline__ void mma_f16(float* c, const uint32_t* a, const uint32_t* b) {
    asm volatile(
        "mma.sync.aligned.m16n8k16.row.col.f32.f16.f16.f32 "
        "{%0,%1,%2,%3}, {%4,%5,%6,%7}, {%8,%9}, {%0,%1,%2,%3};"
        : "+f"(c[0]), "+f"(c[1]), "+f"(c[2]), "+f"(c[3])
        : "r"(a[0]), "r"(a[1]), "r"(a[2]), "r"(a[3]), "r"(b[0]), "r"(b[1]));
}

// grid barrier among chain blocks only: arrive via atomic, wait via acquire-load
__device__ __forceinline__ void grid_barrier(int bar) {
    __threadfence();
    __syncthreads();
    if (threadIdx.x == 0) {
        unsigned my = atomicAdd(&g_count, 1u);
        if (my == (unsigned)(PRE_CHAIN * bar - 1)) {
            atomicAdd(&g_epoch, 1u);
        } else {
            while (true) {
                unsigned e;
                asm volatile("ld.global.acquire.gpu.b32 %0, [%1];" : "=r"(e) : "l"(&g_epoch));
                if (e >= (unsigned)bar) break;
                __nanosleep(128);
            }
        }
    }
    __syncthreads();
}

// ---------------- k_pre: heterogeneous prepass ----------------
// blocks [0,128):          persistent chain (A^T init, 9 doubling rounds, G)
// blocks [128,4224):       ux (u = relu(x@Wu+b), fp16 x)
// blocks [4224,4480):      wht transpose
__global__ __launch_bounds__(256) void k_pre(const float* __restrict__ x,
                                             const float* __restrict__ wu,
                                             const float* __restrict__ wub,
                                             const float* __restrict__ Wh,
                                             const float* __restrict__ A,
                                             const float* __restrict__ Bv) {
    const int gbid = blockIdx.x;
    const int tid = threadIdx.x;

    if (gbid < PRE_CHAIN) {
        // ================= chain path =================
        extern __shared__ __align__(16) float csmem[];
        float* Xs = csmem;
        float* Bs = csmem + 32 * XS_PITCH;
        const int bid = gbid;
        const int ty = tid >> 4, tx = tid & 15;

        // init: block covers 2 k-columns of A^T; block 0 also Ht[0]=B
        {
            int k0 = bid * 2;
#pragma unroll
            for (int h = 0; h < 2; h++) {
                int k = k0 + h;
                g_AT[0][(size_t)k * MEM + tid] = A[(size_t)tid * MEM + k];
            }
            if (bid == 0) g_Ht[tid] = Bv[tid];
        }
        grid_barrier(1);

        for (int r = 0; r <= 8; r++) {
            int n = 1 << r;
            int sel = r & 1;
            int nsq = (r < 8) ? 64 : 0;
            int nrt = (n + 31) / 32;
            int ntiles = nsq + nrt * 8;
            const float* __restrict__ ATin = g_AT[sel];
            for (int t = bid; t < ntiles; t += PRE_CHAIN) {
                const float* Amat; float* Cmat; int rows, tr, tc;
                if (t < nsq) { Amat = ATin; Cmat = g_AT[sel ^ 1]; rows = MEM; tr = t >> 3; tc = t & 7; }
                else { int te = t - nsq; Amat = g_Ht; Cmat = g_Ht + (size_t)n * MEM; rows = n; tr = te >> 3; tc = te & 7; }
                int r0 = tr * 32, c0 = tc * 32;
                __syncthreads();
                for (int q = tid; q < 2048; q += 256) {
                    int row = q >> 6, c4 = (q & 63) * 4;
                    float4 v = make_float4(0.f, 0.f, 0.f, 0.f);
                    if (r0 + row < rows) v = *(const float4*)(Amat + (size_t)(r0 + row) * MEM + c4);
                    *(float4*)&Xs[row * XS_PITCH + c4] = v;
                    int brow = q >> 3, bc4 = (q & 7) * 4;
                    *(float4*)&Bs[brow * 32 + bc4] = *(const float4*)(ATin + (size_t)brow * MEM + c0 + bc4);
                }
                __syncthreads();
                float acc[2][2] = {};
#pragma unroll 8
                for (int k = 0; k < MEM; k++) {
                    float a0 = Xs[(ty * 2) * XS_PITCH + k], a1 = Xs[(ty * 2 + 1) * XS_PITCH + k];
                    float b0 = Bs[k * 32 + tx * 2],         b1 = Bs[k * 32 + tx * 2 + 1];
                    acc[0][0] = fmaf(a0, b0, acc[0][0]); acc[0][1] = fmaf(a0, b1, acc[0][1]);
                    acc[1][0] = fmaf(a1, b0, acc[1][0]); acc[1][1] = fmaf(a1, b1, acc[1][1]);
                }
#pragma unroll
                for (int i = 0; i < 2; i++) {
                    int rr = r0 + ty * 2 + i;
                    if (rr < rows) {
                        Cmat[(size_t)rr * MEM + c0 + tx * 2]     = acc[i][0];
                        Cmat[(size_t)rr * MEM + c0 + tx * 2 + 1] = acc[i][1];
                    }
                }
            }
            grid_barrier(r + 2);
        }

        // G phase: G = Ht @ Wh_m -> gt[j][d] fp16
        for (int t = bid; t < 256; t += PRE_CHAIN) {
            int tr = t >> 4, tc = t & 15;
            int d0 = tr * 32, j0 = tc * 32;
            __syncthreads();
            for (int q = tid; q < 2048; q += 256) {
                int row = q >> 6, c4 = (q & 63) * 4;
                *(float4*)&Xs[row * XS_PITCH + c4] = *(const float4*)(g_Ht + (size_t)(d0 + row) * MEM + c4);
                int brow = q >> 3, bc4 = (q & 7) * 4;
                *(float4*)&Bs[brow * 32 + bc4] = *(const float4*)(Wh + (size_t)brow * HID + j0 + bc4);
            }
            __syncthreads();
            float acc[2][2] = {};
#pragma unroll 8
            for (int k = 0; k < MEM; k++) {
                float a0 = Xs[(ty * 2) * XS_PITCH + k], a1 = Xs[(ty * 2 + 1) * XS_PITCH + k];
                float b0 = Bs[k * 32 + tx * 2],         b1 = Bs[k * 32 + tx * 2 + 1];
                acc[0][0] = fmaf(a0, b0, acc[0][0]); acc[0][1] = fmaf(a0, b1, acc[0][1]);
                acc[1][0] = fmaf(a1, b0, acc[1][0]); acc[1][1] = fmaf(a1, b1, acc[1][1]);
            }
#pragma unroll
            for (int i = 0; i < 2; i++)
#pragma unroll
                for (int jj = 0; jj < 2; jj++) {
                    int d = d0 + ty * 2 + i, j = j0 + tx * 2 + jj;
                    g_gt[(size_t)j * SEQ + d] = __float2half(acc[i][jj]);
                }
        }
    } else if (gbid < PRE_CHAIN + UX_BLOCKS) {
        // ================= ux path =================
        int row = (gbid - PRE_CHAIN) * 8 + (tid >> 5);   // [0, 32768)
        int lane = tid & 31;
        const float4* xr = (const float4*)(x + (size_t)row * DIN);
        const float4* wr = (const float4*)wu;
        float s = 0.f;
#pragma unroll
        for (int i = 0; i < 4; i++) {
            float4 v = xr[lane + 32 * i];
            float4 w = wr[lane + 32 * i];
            s += v.x * w.x + v.y * w.y + v.z * w.z + v.w * w.w;
            size_t off = (size_t)row * DIN + (lane + 32 * i) * 4;
            __half2 ha = {__float2half(v.x), __float2half(v.y)};
            __half2 hb = {__float2half(v.z), __float2half(v.w)};
            *(__half2*)(g_xh + off) = ha; *(__half2*)(g_xh + off + 2) = hb;
        }
#pragma unroll
        for (int o = 16; o; o >>= 1) s += __shfl_xor_sync(0xffffffffu, s, o);
        if (lane == 0) {
            float u = fmaxf(s + wub[0], 0.f);
            int b = row >> 9, t = row & 511;
            g_urh[b * URPAD + (511 - t)] = __float2half(u);
            if (t < 128) g_urh[b * URPAD + 512 + t] = __float2half(0.f);
        }
    } else {
        // ================= wht transpose path =================
        __shared__ float tile[32][33];
        int t = gbid - PRE_CHAIN - UX_BLOCKS;         // [0,256)
        int kb = t & 15, jb = t >> 4;
        int tx = tid & 31, ty = tid >> 5;
        for (int yy = ty; yy < 32; yy += 8)
            tile[yy][tx] = Wh[(size_t)(MEM + kb * 32 + yy) * HID + jb * 32 + tx];
        __syncthreads();
        for (int yy = ty; yy < 32; yy += 8) {
            float v = tile[tx][yy];
            int j = jb * 32 + yy, k = kb * 32 + tx;
            g_wht[(size_t)j * DIN + k] = __float2half(v);
        }
    }
}

// ---------------- k_main: single-product fp16 fused GEMM, K=64 chunks ----------------
__device__ __forceinline__ void cp_tile64(uint32_t sdst, const __half* __restrict__ g,
                                          int stride, int tid) {
#pragma unroll
    for (int it = 0; it < 4; it++) {
        int q = tid + it * 256;
        int row = q >> 3, ch = q & 7;
        cp16(sdst + row * RSB + ch * 16, g + (size_t)row * stride + ch * 8);
    }
}

__global__ __launch_bounds__(256, 2) void k_main(const float* __restrict__ Whb,
                                                 float* __restrict__ out, int write_hn) {
    extern __shared__ __align__(128) char smem[];
    const int b = blockIdx.z;
    const int t0 = blockIdx.y * 128;
    const int j0 = blockIdx.x * 128;
    const int tid = threadIdx.x;
    const int lane = tid & 31;
    const int warp_m = (tid >> 5) & 1;
    const int warp_n = tid >> 6;
    const uint32_t sbase = smem_to_u32(smem);

    {
        const uint32_t* gh = (const uint32_t*)(g_urh + (size_t)b * URPAD);
        uint32_t* sh = (uint32_t*)(smem + URS_OFF);
        for (int q = tid; q < 320; q += 256) sh[q] = gh[q];
    }
    __syncthreads();
    const uint32_t* ursh32 = (const uint32_t*)(smem + URS_OFF);

    const __half* xh = g_xh + ((size_t)(b * SEQ + t0)) * DIN;
    const __half* wt = g_wht + (size_t)j0 * DIN;
    const __half* gt = g_gt + (size_t)j0 * SEQ;

    const int nchunks = 10 + 2 * blockIdx.y;

    auto fill = [&](int i, int p) {
        uint32_t sb = sbase + p * BUFB;
        char* sc = smem + p * BUFB;
        if (i < 8) {
            int k0 = i * 64;
            cp_tile64(sb,         xh + k0, DIN, tid);
            cp_tile64(sb + TILEB, wt + k0, DIN, tid);
        } else {
            int d0 = (i - 8) * 64;
            cp_tile64(sb + TILEB, gt + d0, SEQ, tid);
            int r = tid >> 1, hf = tid & 1;
            int s0 = 511 - (t0 + r) + d0 + hf * 32;
            int base = s0 >> 1, par = s0 & 1;
            uint32_t w[16];
            uint32_t w0 = ursh32[base];
#pragma unroll
            for (int c = 0; c < 16; c++) {
                uint32_t w1 = ursh32[base + c + 1];
                w[c] = par ? __byte_perm(w0, w1, 0x5432) : w0;
                w0 = w1;
            }
#pragma unroll
            for (int q = 0; q < 4; q++)
                *(uint4*)(sc + r * RSB + hf * 64 + q * 16) =
                    make_uint4(w[q * 4], w[q * 4 + 1], w[q * 4 + 2], w[q * 4 + 3]);
        }
    };

    float acc[4][4][4];
#pragma unroll
    for (int mi = 0; mi < 4; mi++)
#pragma unroll
        for (int ni = 0; ni < 4; ni++)
#pragma unroll
            for (int e = 0; e < 4; e++) acc[mi][ni][e] = 0.f;

    fill(0, 0);
    CP_COMMIT();

    const uint32_t a_base_off = (warp_m * 64 + (lane & 15)) * RSB + ((lane >> 4) << 4);
    const uint32_t b_base_off = TILEB + (warp_n * 32 + (lane & 15)) * RSB + ((lane >> 4) << 4);

    for (int i = 0; i < nchunks; i++) {
        int p = i & 1;
        if (i + 1 < nchunks) { fill(i + 1, p ^ 1); CP_COMMIT(); CP_WAIT1(); }
        else CP_WAIT0();
        __syncthreads();

        uint32_t base = sbase + p * BUFB;
#pragma unroll
        for (int ks = 0; ks < 4; ks++) {
            uint32_t bh[4][2];
            {
                uint32_t r[4];
                uint32_t baddr = base + b_base_off + ks * 32;
                ldsm4(r, baddr);
                bh[0][0] = r[0]; bh[0][1] = r[2];
                bh[1][0] = r[1]; bh[1][1] = r[3];
                ldsm4(r, baddr + 16 * RSB);
                bh[2][0] = r[0]; bh[2][1] = r[2];
                bh[3][0] = r[1]; bh[3][1] = r[3];
            }
            uint32_t a[4][4];
            uint32_t aaddr = base + a_base_off + ks * 32;
#pragma unroll
            for (int mi = 0; mi < 4; mi++) ldsm4(a[mi], aaddr + mi * 16 * RSB);
#pragma unroll
            for (int mi = 0; mi < 4; mi++)
#pragma unroll
                for (int ni = 0; ni < 4; ni++)
                    mma_f16(acc[mi][ni], a[mi], bh[ni]);
        }
        __syncthreads();
    }

    // ---- epilogue ----
    const int g4 = lane >> 2, t4 = lane & 3;
    const size_t HN_BASE = (size_t)NBATCH * SEQ * HID;
    float2 bias[4];
#pragma unroll
    for (int ni = 0; ni < 4; ni++)
        bias[ni] = *(const float2*)(Whb + j0 + warp_n * 32 + ni * 8 + t4 * 2);
#pragma unroll
    for (int mi = 0; mi < 4; mi++) {
        int ta = t0 + warp_m * 64 + mi * 16 + g4;
        int tb = ta + 8;
        size_t rowa = ((size_t)b * SEQ + ta) * HID;
        size_t rowb = ((size_t)b * SEQ + tb) * HID;
#pragma unroll
        for (int ni = 0; ni < 4; ni++) {
            int j = j0 + warp_n * 32 + ni * 8 + t4 * 2;
            float2 v0, v1;
            v0.x = fmaxf(acc[mi][ni][0] + bias[ni].x, 0.f);
            v0.y = fmaxf(acc[mi][ni][1] + bias[ni].y, 0.f);
            v1.x = fmaxf(acc[mi][ni][2] + bias[ni].x, 0.f);
            v1.y = fmaxf(acc[mi][ni][3] + bias[ni].y, 0.f);
            *(float2*)(out + rowa + j) = v0;
            *(float2*)(out + rowb + j) = v1;
            if (write_hn && tb == SEQ - 1)
                *(float2*)(out + HN_BASE + (size_t)b * HID + j) = v1;
        }
    }

    // reset chain-barrier state for the next graph replay (deterministic:
    // counters are 0 at module load and after every k_main execution)
    if (blockIdx.x == 0 && blockIdx.y == 0 && blockIdx.z == 0 && tid == 0) {
        g_count = 0;
        g_epoch = 0;
    }
}

// ---------------- launch ----------------
extern "C" void kernel_launch(void* const* d_in, const int* in_sizes, int n_in,
                              void* d_out, int out_size) {
    const float* x    = (const float*)d_in[0];
    const float* Wu_w = (const float*)d_in[1];
    const float* Wu_b = (const float*)d_in[2];
    const float* Wh_w = (const float*)d_in[3];
    const float* Wh_b = (const float*)d_in[4];
    const float* A    = (const float*)d_in[5];
    const float* B    = (const float*)d_in[6];
    float* out = (float*)d_out;

    int write_hn = (out_size >= NBATCH * SEQ * HID + NBATCH * HID) ? 1 : 0;

    static int smem_set = 0;
    if (!smem_set) {
        cudaFuncSetAttribute(k_main, cudaFuncAttributeMaxDynamicSharedMemorySize, SMEM_DYN);
        cudaFuncSetAttribute(k_pre, cudaFuncAttributeMaxDynamicSharedMemorySize, CHAIN_SMEM);
        smem_set = 1;
    }

    k_pre<<<PRE_GRID, 256, CHAIN_SMEM>>>(x, Wu_w, Wu_b, Wh_w, A, B);
    k_main<<<dim3(HID / 128, SEQ / 128, NBATCH), 256, SMEM_DYN>>>(Wh_b, out, write_hn);
}